// round 8
// baseline (speedup 1.0000x reference)
#include <cuda_runtime.h>
#include <cuda_bf16.h>
#include <stdint.h>
#include <math.h>

typedef __nv_bfloat16 bf16;
typedef unsigned int u32;

// ---------------- problem constants ----------------
#define BB 4
#define CCH 512
#define CIn 256
#define NN 12544
#define MMr 1568          // real pooled positions
#define MP_Y 1600         // pad for y-GEMM K (50*32)
#define MP_F 1664         // pad for f-GEMM N (13*128)
#define EPS 1e-5f

// ---------------- scratch layout (byte offsets) ----------------
#define XT_HI    0ULL
#define XT_LO    51380224ULL
#define F_OFF    0ULL
#define CONV_HI  334987264ULL
#define CONV_LO  412057600ULL
#define P_HI     334987264ULL
#define P_LO     495550464ULL
#define Y_HI     0ULL
#define Y_LO     25690112ULL
#define WY_OFF   102760448ULL
#define GT_HI    656113664ULL
#define GT_LO    659390464ULL
#define PHP_HI   662667264ULL
#define PHP_LO   666075136ULL
#define W8_OFF   669483008ULL
#define BCAT_OFF 671580160ULL
#define PART_OFF 671583232ULL
#define SCRATCH_BYTES 672000000ULL

#define CONV_PLANE 25690112ULL   // bytes per conv plane (4*NN*256*2)

__device__ __align__(128) unsigned char d_scratch[SCRATCH_BYTES];
__device__ __align__(16) float d_stats[2 * CCH];

// ---------------- helpers ----------------
__device__ __forceinline__ u32 smem_u32(const void* p) {
    u32 a;
    asm("{ .reg .u64 t; cvta.to.shared.u64 t, %1; cvt.u32.u64 %0, t; }" : "=r"(a) : "l"(p));
    return a;
}
__device__ __forceinline__ void ldsm4(u32& r0, u32& r1, u32& r2, u32& r3, u32 addr) {
    asm volatile("ldmatrix.sync.aligned.m8n8.x4.shared.b16 {%0,%1,%2,%3}, [%4];"
                 : "=r"(r0), "=r"(r1), "=r"(r2), "=r"(r3) : "r"(addr));
}
__device__ __forceinline__ void mma16816(float* d, const u32* a, const u32* b) {
    asm volatile(
        "mma.sync.aligned.m16n8k16.row.col.f32.bf16.bf16.f32 "
        "{%0,%1,%2,%3},{%4,%5,%6,%7},{%8,%9},{%0,%1,%2,%3};"
        : "+f"(d[0]), "+f"(d[1]), "+f"(d[2]), "+f"(d[3])
        : "r"(a[0]), "r"(a[1]), "r"(a[2]), "r"(a[3]), "r"(b[0]), "r"(b[1]));
}
__device__ __forceinline__ u32 sw128(u32 off) { return off ^ ((off >> 3) & 0x70); }
__device__ __forceinline__ void cp16(u32 dst, const void* src) {
    asm volatile("cp.async.cg.shared.global [%0], [%1], 16;" :: "r"(dst), "l"(src));
}
#define CP_COMMIT() asm volatile("cp.async.commit_group;" ::: "memory")
#define CP_WAIT1()  asm volatile("cp.async.wait_group 1;" ::: "memory")

// ---------------- fused-split cp.async bf16 GEMM ----------------
// D = A_hi*B_hi^T + A_hi*B_lo^T + A_lo*B_hi^T, all 3 products per k-chunk.
// BK=32. Each smem stage row (128B) packs hi chunk (bytes 0..63) and lo chunk
// (bytes 64..127) -> same SW128 swizzle. Stage = 16KB A + 16KB B; 3 stages.
// CTA tile 128x128, 8 warps (2M x 4N), 2 CTAs/SM.
// EPI 0: fp32 C + optional col bias. EPI 1: bf16 hi/lo planes.
// SEG 1: 256-col segmented output (fused conv).
template <int EPI, int SEG>
__global__ __launch_bounds__(256, 2)
void tgemm(const bf16* __restrict__ Ahi, const bf16* __restrict__ Alo,
           const bf16* __restrict__ Bhi, const bf16* __restrict__ Blo,
           float* __restrict__ Cf, bf16* __restrict__ Chi, bf16* __restrict__ Clo,
           const float* __restrict__ bias,
           int K, int ldc, long long sA, long long sB, long long sC, long long segS)
{
    extern __shared__ __align__(1024) unsigned char sm[];
    const u32 sbase = smem_u32(sm);
    const int tid = threadIdx.x;
    const int wid = tid >> 5;
    const int lane = tid & 31;
    const int m0 = blockIdx.x * 128;
    const int n0 = blockIdx.y * 128;
    const long long bz = blockIdx.z;
    Ahi += bz * sA; Alo += bz * sA;
    Bhi += bz * sB; Blo += bz * sB;

    const int Kc = K >> 5;   // 32-K chunks

    // ---- cp.async mapping: rowL = tid>>1; half: 0 -> hi plane, 1 -> lo plane ----
    const int rowL = tid >> 1;
    const int half = tid & 1;
    const bf16* srcA = half ? Alo : Ahi;
    const bf16* srcB = half ? Blo : Bhi;
    const long long gA = (long long)(m0 + rowL) * K;
    const long long gB = (long long)(n0 + rowL) * K;
    u32 soff[4];
#pragma unroll
    for (int i = 0; i < 4; i++)
        soff[i] = sw128((u32)rowL * 128 + (u32)half * 64 + i * 16);

#define ISSUE(it2) do { \
    const long long _k0 = (long long)(it2) << 5; \
    const u32 _sa = sbase + ((it2) % 3) * 32768u; \
    const u32 _sb = _sa + 16384u; \
    _Pragma("unroll") \
    for (int _i = 0; _i < 4; _i++) { \
        cp16(_sa + soff[_i], srcA + gA + _k0 + _i * 8); \
        cp16(_sb + soff[_i], srcB + gB + _k0 + _i * 8); \
    } \
} while (0)

    // ---- per-lane ldmatrix bases ----
    const int wm = wid >> 2;
    const int wn = wid & 3;
    const int rowA = wm * 64 + ((lane >> 3) & 1) * 8 + (lane & 7);
    const u32 kbA = (u32)(lane >> 4) * 16;
    const int rowB = wn * 32 + ((lane >> 4) & 1) * 8 + (lane & 7);
    const u32 kbB = (u32)((lane >> 3) & 1) * 16;

    float acc[4][4][4];
#pragma unroll
    for (int mt = 0; mt < 4; mt++)
#pragma unroll
        for (int nt = 0; nt < 4; nt++)
#pragma unroll
            for (int q = 0; q < 4; q++) acc[mt][nt][q] = 0.f;

    // prologue: stages 0,1
    ISSUE(0); CP_COMMIT();
    ISSUE(1); CP_COMMIT();

    for (int it = 0; it < Kc; it++) {
        CP_WAIT1();
        __syncthreads();
        if (it + 2 < Kc) ISSUE(it + 2);
        CP_COMMIT();

        const u32 sA32 = sbase + (it % 3) * 32768u;
        const u32 sB32 = sA32 + 16384u;
#pragma unroll
        for (int kk = 0; kk < 2; kk++) {
            // hi fragments (bytes kk*32 .. kk*32+31 within the 0..63 hi half)
            u32 ah[4][4], bh[2][4];
#pragma unroll
            for (int mt = 0; mt < 4; mt++) {
                u32 off = (u32)(rowA + mt * 16) * 128 + (u32)kk * 32 + kbA;
                ldsm4(ah[mt][0], ah[mt][1], ah[mt][2], ah[mt][3], sA32 + sw128(off));
            }
#pragma unroll
            for (int nt2 = 0; nt2 < 2; nt2++) {
                u32 off = (u32)(rowB + nt2 * 16) * 128 + (u32)kk * 32 + kbB;
                ldsm4(bh[nt2][0], bh[nt2][1], bh[nt2][2], bh[nt2][3], sB32 + sw128(off));
            }
            // hi*hi
#pragma unroll
            for (int mt = 0; mt < 4; mt++)
#pragma unroll
                for (int nt = 0; nt < 4; nt++)
                    mma16816(acc[mt][nt], ah[mt], &bh[nt >> 1][(nt & 1) * 2]);
            // hi*lo (B lo half at byte offset +64)
            {
                u32 bl[2][4];
#pragma unroll
                for (int nt2 = 0; nt2 < 2; nt2++) {
                    u32 off = (u32)(rowB + nt2 * 16) * 128 + 64 + (u32)kk * 32 + kbB;
                    ldsm4(bl[nt2][0], bl[nt2][1], bl[nt2][2], bl[nt2][3], sB32 + sw128(off));
                }
#pragma unroll
                for (int mt = 0; mt < 4; mt++)
#pragma unroll
                    for (int nt = 0; nt < 4; nt++)
                        mma16816(acc[mt][nt], ah[mt], &bl[nt >> 1][(nt & 1) * 2]);
            }
            // lo*hi (A lo half at byte offset +64)
            {
                u32 al[4][4];
#pragma unroll
                for (int mt = 0; mt < 4; mt++) {
                    u32 off = (u32)(rowA + mt * 16) * 128 + 64 + (u32)kk * 32 + kbA;
                    ldsm4(al[mt][0], al[mt][1], al[mt][2], al[mt][3], sA32 + sw128(off));
                }
#pragma unroll
                for (int mt = 0; mt < 4; mt++)
#pragma unroll
                    for (int nt = 0; nt < 4; nt++)
                        mma16816(acc[mt][nt], al[mt], &bh[nt >> 1][(nt & 1) * 2]);
            }
        }
    }
#undef ISSUE

    // ---- epilogue ----
    const int r0 = m0 + wm * 64 + (lane >> 2);
    const int cb0 = n0 + wn * 32 + (lane & 3) * 2;
    const long long obase = bz * sC + (SEG ? (long long)(n0 >> 8) * segS : 0LL);
#pragma unroll
    for (int nt = 0; nt < 4; nt++) {
        const int c = cb0 + nt * 8;
        const int cl = SEG ? (c & 255) : c;
        const float b0v = bias ? bias[c] : 0.f;
        const float b1v = bias ? bias[c + 1] : 0.f;
#pragma unroll
        for (int mt = 0; mt < 4; mt++) {
            const long long ra = r0 + mt * 16;
            const long long rb = ra + 8;
            float v0 = acc[mt][nt][0] + b0v;
            float v1 = acc[mt][nt][1] + b1v;
            float v2 = acc[mt][nt][2] + b0v;
            float v3 = acc[mt][nt][3] + b1v;
            if (EPI == 0) {
                float* base = Cf + obase;
                *(float2*)(base + ra * ldc + cl) = make_float2(v0, v1);
                *(float2*)(base + rb * ldc + cl) = make_float2(v2, v3);
            } else {
                bf16 h0 = __float2bfloat16(v0), h1 = __float2bfloat16(v1);
                bf16 h2 = __float2bfloat16(v2), h3 = __float2bfloat16(v3);
                bf16 l0 = __float2bfloat16(v0 - __bfloat162float(h0));
                bf16 l1 = __float2bfloat16(v1 - __bfloat162float(h1));
                bf16 l2 = __float2bfloat16(v2 - __bfloat162float(h2));
                bf16 l3 = __float2bfloat16(v3 - __bfloat162float(h3));
                bf16* hb = Chi + obase;
                bf16* lb = Clo + obase;
                *(u32*)(hb + ra * ldc + cl) = (u32)__bfloat16_as_ushort(h0) | ((u32)__bfloat16_as_ushort(h1) << 16);
                *(u32*)(hb + rb * ldc + cl) = (u32)__bfloat16_as_ushort(h2) | ((u32)__bfloat16_as_ushort(h3) << 16);
                *(u32*)(lb + ra * ldc + cl) = (u32)__bfloat16_as_ushort(l0) | ((u32)__bfloat16_as_ushort(l1) << 16);
                *(u32*)(lb + rb * ldc + cl) = (u32)__bfloat16_as_ushort(l2) | ((u32)__bfloat16_as_ushort(l3) << 16);
            }
        }
    }
}

// ---------------- fp32 -> bf16 hi/lo split ----------------
__global__ void split_kernel(const float* __restrict__ src, bf16* __restrict__ hi,
                             bf16* __restrict__ lo, int n)
{
    int i = blockIdx.x * 256 + threadIdx.x;
    if (i < n) {
        float v = src[i];
        bf16 h = __float2bfloat16(v);
        hi[i] = h;
        lo[i] = __float2bfloat16(v - __bfloat162float(h));
    }
}

// ---------------- zero fill ----------------
__global__ void zero_kernel(float4* __restrict__ p, long long n4)
{
    long long i = (long long)blockIdx.x * 256 + threadIdx.x;
    const long long stride = (long long)gridDim.x * 256;
    for (; i < n4; i += stride) p[i] = make_float4(0.f, 0.f, 0.f, 0.f);
}

// ---------------- transpose x (b,512,N) -> xT hi/lo (b,N,512) ----------------
__global__ void xpose_kernel(const float* __restrict__ x, bf16* __restrict__ xhi,
                             bf16* __restrict__ xlo)
{
    __shared__ float t[32][33];
    const int b = blockIdx.z;
    const int n0 = blockIdx.x * 32;
    const int c0 = blockIdx.y * 32;
    const int tx = threadIdx.x, ty = threadIdx.y;
    const float* xb = x + (long long)b * CCH * NN;
#pragma unroll
    for (int k = 0; k < 4; k++)
        t[ty + k * 8][tx] = xb[(long long)(c0 + ty + k * 8) * NN + n0 + tx];
    __syncthreads();
    bf16* hb = xhi + (long long)b * NN * CCH;
    bf16* lb = xlo + (long long)b * NN * CCH;
#pragma unroll
    for (int k = 0; k < 4; k++) {
        float v = t[tx][ty + k * 8];
        long long o = (long long)(n0 + ty + k * 8) * CCH + c0 + tx;
        bf16 h = __float2bfloat16(v);
        hb[o] = h;
        lb[o] = __float2bfloat16(v - __bfloat162float(h));
    }
}

// ---------------- 2x2x2 maxpool (from bf16 hi/lo conv planes) + split ----------------
__global__ void pool_kernel(const bf16* __restrict__ gH, const bf16* __restrict__ gL,
                            const bf16* __restrict__ pH, const bf16* __restrict__ pL,
                            bf16* __restrict__ gThi, bf16* __restrict__ gTlo,
                            bf16* __restrict__ phphi, bf16* __restrict__ phplo)
{
    const int m = blockIdx.x;      // 0..1567
    const int b = blockIdx.y;
    const int ci = threadIdx.x;    // 0..255
    const int tp = m / 196;
    const int r = m % 196;
    const int hp = r / 14;
    const int wp = r % 14;
    const long long bb = (long long)b * NN;
    float gm = -1e30f, pm = -1e30f;
#pragma unroll
    for (int dt = 0; dt < 2; dt++)
#pragma unroll
        for (int dh = 0; dh < 2; dh++)
#pragma unroll
            for (int dw = 0; dw < 2; dw++) {
                const long long n = (long long)(2 * tp + dt) * 784 + (2 * hp + dh) * 28 + (2 * wp + dw);
                const long long o = (bb + n) * CIn + ci;
                float gv = __bfloat162float(gH[o]) + __bfloat162float(gL[o]);
                float pv = __bfloat162float(pH[o]) + __bfloat162float(pL[o]);
                gm = fmaxf(gm, gv);
                pm = fmaxf(pm, pv);
            }
    {
        long long o = ((long long)b * MP_F + m) * CIn + ci;
        bf16 h = __float2bfloat16(pm);
        phphi[o] = h;
        phplo[o] = __float2bfloat16(pm - __bfloat162float(h));
    }
    {
        long long o = ((long long)b * CIn + ci) * MP_Y + m;
        bf16 h = __float2bfloat16(gm);
        gThi[o] = h;
        gTlo[o] = __float2bfloat16(gm - __bfloat162float(h));
    }
}

// ---------------- softmax: single global read via smem row cache ----------------
__global__ __launch_bounds__(256)
void softmax_kernel(const float* __restrict__ f, bf16* __restrict__ phi_,
                    bf16* __restrict__ plo_)
{
    __shared__ float row[MMr];
    __shared__ float red[8];
    const long long r = blockIdx.x;
    const float* p = f + r * MP_F;
    bf16* oh = phi_ + r * MP_Y;
    bf16* ol = plo_ + r * MP_Y;
    const int tid = threadIdx.x;
    const int wid = tid >> 5, lane = tid & 31;

    float mx = -1e30f;
    for (int i = tid; i < MMr; i += 256) {
        float v = p[i];
        row[i] = v;
        mx = fmaxf(mx, v);
    }
#pragma unroll
    for (int s = 16; s > 0; s >>= 1) mx = fmaxf(mx, __shfl_xor_sync(~0u, mx, s));
    if (lane == 0) red[wid] = mx;
    __syncthreads();
    {
        float t = red[lane & 7];
#pragma unroll
        for (int s = 4; s > 0; s >>= 1) t = fmaxf(t, __shfl_xor_sync(~0u, t, s));
        mx = t;
    }

    float sum = 0.f;
    for (int i = tid; i < MMr; i += 256) {
        float e = __expf(row[i] - mx);
        row[i] = e;
        sum += e;
    }
#pragma unroll
    for (int s = 16; s > 0; s >>= 1) sum += __shfl_xor_sync(~0u, sum, s);
    __syncthreads();
    if (lane == 0) red[wid] = sum;
    __syncthreads();
    {
        float t = red[lane & 7];
#pragma unroll
        for (int s = 4; s > 0; s >>= 1) t += __shfl_xor_sync(~0u, t, s);
        sum = t;
    }
    const float inv = 1.f / sum;

    for (int i = tid; i < MMr; i += 256) {
        float v = row[i] * inv;
        bf16 h = __float2bfloat16(v);
        oh[i] = h;
        ol[i] = __float2bfloat16(v - __bfloat162float(h));
    }
    if (tid < MP_Y - MMr) {
        oh[MMr + tid] = __ushort_as_bfloat16(0);
        ol[MMr + tid] = __ushort_as_bfloat16(0);
    }
}

// ---------------- BN stats: partial sums then finalize ----------------
__global__ void stats_part(const float* __restrict__ wy, float* __restrict__ part)
{
    const int c = blockIdx.x * 128 + threadIdx.x;
    const int rb = blockIdx.y;                      // 98 row blocks of 512 rows
    const float* p = wy + (long long)rb * 512 * CCH + c;
    float s = 0.f, ss = 0.f;
    for (int r = 0; r < 512; r++) {
        float v = p[(long long)r * CCH];
        s += v;
        ss += v * v;
    }
    part[(long long)rb * 1024 + c] = s;
    part[(long long)rb * 1024 + 512 + c] = ss;
}

__global__ void stats_fin(const float* __restrict__ part, float* __restrict__ stats)
{
    const int c = threadIdx.x;   // 512
    float s = 0.f, ss = 0.f;
    for (int r = 0; r < 98; r++) {
        s += part[r * 1024 + c];
        ss += part[r * 1024 + 512 + c];
    }
    const float cnt = (float)BB * (float)NN;
    const float mean = s / cnt;
    const float var = ss / cnt - mean * mean;
    stats[c] = mean;
    stats[CCH + c] = rsqrtf(var + EPS);
}

// ---------------- final: transpose wy (b,n,c)->(b,c,n), BN affine + residual ----------------
__global__ void final_kernel(const float* __restrict__ wy, const float* __restrict__ x,
                             const float* __restrict__ gamma, const float* __restrict__ beta,
                             const float* __restrict__ stats, float* __restrict__ out)
{
    __shared__ float t[32][33];
    const int b = blockIdx.z;
    const int n0 = blockIdx.x * 32;
    const int c0 = blockIdx.y * 32;
    const int tx = threadIdx.x, ty = threadIdx.y;
    const float* wb = wy + (long long)b * NN * CCH;
#pragma unroll
    for (int k = 0; k < 4; k++)
        t[ty + k * 8][tx] = wb[(long long)(n0 + ty + k * 8) * CCH + c0 + tx];
    __syncthreads();
#pragma unroll
    for (int k = 0; k < 4; k++) {
        const int c = c0 + ty + k * 8;
        const float mean = stats[c];
        const float rstd = stats[CCH + c];
        const float gs = gamma[c] * rstd;
        const float off = beta[c] - mean * gs;
        const long long o = ((long long)b * CCH + c) * NN + n0 + tx;
        out[o] = t[tx][ty + k * 8] * gs + off + x[o];
    }
}

// ---------------- launch ----------------
extern "C" void kernel_launch(void* const* d_in, const int* in_sizes, int n_in,
                              void* d_out, int out_size)
{
    const float* x       = (const float*)d_in[0];
    const float* g_w     = (const float*)d_in[1];
    const float* g_b     = (const float*)d_in[2];
    const float* theta_w = (const float*)d_in[3];
    const float* theta_b = (const float*)d_in[4];
    const float* phi_w   = (const float*)d_in[5];
    const float* phi_b   = (const float*)d_in[6];
    const float* W_w     = (const float*)d_in[7];
    // d_in[8] = W_b: constant channel bias cancels exactly in training-mode BN — skipped.
    const float* gamma   = (const float*)d_in[9];
    const float* beta    = (const float*)d_in[10];
    float* out = (float*)d_out;

    unsigned char* S = nullptr;
    float* stats = nullptr;
    cudaGetSymbolAddress((void**)&S, d_scratch);
    cudaGetSymbolAddress((void**)&stats, d_stats);

    bf16* xt_hi  = (bf16*)(S + XT_HI);
    bf16* xt_lo  = (bf16*)(S + XT_LO);
    float* f     = (float*)(S + F_OFF);
    bf16* conv_hi = (bf16*)(S + CONV_HI);   // [theta | g | phi] planes, each (b,n,256)
    bf16* conv_lo = (bf16*)(S + CONV_LO);
    bf16* th_hi  = conv_hi;                 // seg 0
    bf16* th_lo  = conv_lo;
    bf16* gc_hi  = (bf16*)(S + CONV_HI + CONV_PLANE);       // seg 1
    bf16* gc_lo  = (bf16*)(S + CONV_LO + CONV_PLANE);
    bf16* pc_hi  = (bf16*)(S + CONV_HI + 2 * CONV_PLANE);   // seg 2
    bf16* pc_lo  = (bf16*)(S + CONV_LO + 2 * CONV_PLANE);
    bf16* p_hi   = (bf16*)(S + P_HI);
    bf16* p_lo   = (bf16*)(S + P_LO);
    bf16* y_hi   = (bf16*)(S + Y_HI);
    bf16* y_lo   = (bf16*)(S + Y_LO);
    float* wy    = (float*)(S + WY_OFF);
    bf16* gt_hi  = (bf16*)(S + GT_HI);
    bf16* gt_lo  = (bf16*)(S + GT_LO);
    bf16* php_hi = (bf16*)(S + PHP_HI);
    bf16* php_lo = (bf16*)(S + PHP_LO);
    bf16* wcat_hi = (bf16*)(S + W8_OFF);                    // 768 x 512
    bf16* wcat_lo = (bf16*)(S + W8_OFF + 786432);
    bf16* ww_hi  = (bf16*)(S + W8_OFF + 1572864);           // 512 x 256
    bf16* ww_lo  = (bf16*)(S + W8_OFF + 1835008);
    float* bcat  = (float*)(S + BCAT_OFF);                  // 768
    float* part  = (float*)(S + PART_OFF);

    const int smem = 3 * 32768;   // 96 KB: 3-stage ring
    cudaFuncSetAttribute(tgemm<0, 0>, cudaFuncAttributeMaxDynamicSharedMemorySize, smem);
    cudaFuncSetAttribute(tgemm<1, 0>, cudaFuncAttributeMaxDynamicSharedMemorySize, smem);
    cudaFuncSetAttribute(tgemm<1, 1>, cudaFuncAttributeMaxDynamicSharedMemorySize, smem);

    // concat weight splits: [theta; g; phi] -> wcat (768 x 512)
    split_kernel<<<512, 256>>>(theta_w, wcat_hi, wcat_lo, 131072);
    split_kernel<<<512, 256>>>(g_w, wcat_hi + 131072, wcat_lo + 131072, 131072);
    split_kernel<<<512, 256>>>(phi_w, wcat_hi + 262144, wcat_lo + 262144, 131072);
    split_kernel<<<512, 256>>>(W_w, ww_hi, ww_lo, 131072);

    // concat biases
    cudaMemcpyAsync(bcat, theta_b, 256 * 4, cudaMemcpyDeviceToDevice);
    cudaMemcpyAsync(bcat + 256, g_b, 256 * 4, cudaMemcpyDeviceToDevice);
    cudaMemcpyAsync(bcat + 512, phi_b, 256 * 4, cudaMemcpyDeviceToDevice);

    // zero gt/php pad region (13,369,344 B contiguous at GT_HI)
    zero_kernel<<<2048, 256>>>((float4*)(S + GT_HI), 13369344 / 16);

    // transpose + split x -> xT (b, n, 512)
    xpose_kernel<<<dim3(NN / 32, CCH / 32, BB), dim3(32, 8)>>>(x, xt_hi, xt_lo);

    const long long sXT = (long long)NN * CCH;
    const long long sCI = (long long)NN * CIn;

    // fused conv: [theta|g|phi] = xT @ wcat^T -> bf16 hi/lo planes, seg-routed
    tgemm<1, 1><<<dim3(98, 6, BB), 256, smem>>>(xt_hi, xt_lo, wcat_hi, wcat_lo,
        nullptr, conv_hi, conv_lo, bcat, CCH, CIn, sXT, 0LL, sCI, 4LL * sCI);

    // pool + split: gT (b,256,1600), php (b,1664,256)
    pool_kernel<<<dim3(MMr, BB), 256>>>(gc_hi, gc_lo, pc_hi, pc_lo,
                                        gt_hi, gt_lo, php_hi, php_lo);

    // f = theta @ phi^T : (b, n, 1664) fp32
    tgemm<0, 0><<<dim3(98, MP_F / 128, BB), 256, smem>>>(th_hi, th_lo, php_hi, php_lo,
        f, nullptr, nullptr, nullptr, CIn, MP_F, sCI, (long long)MP_F * CIn,
        (long long)NN * MP_F, 0LL);

    // softmax -> p hi/lo (b, n, 1600)
    softmax_kernel<<<BB * NN, 256>>>(f, p_hi, p_lo);

    // y = p @ gT^T : (b, n, 256) bf16 planes
    tgemm<1, 0><<<dim3(98, 2, BB), 256, smem>>>(p_hi, p_lo, gt_hi, gt_lo,
        nullptr, y_hi, y_lo, nullptr, MP_Y, CIn, (long long)NN * MP_Y,
        (long long)CIn * MP_Y, sCI, 0LL);

    // wy = y @ W_w^T : (b, n, 512) fp32  (W_b dropped: cancels in BN)
    tgemm<0, 0><<<dim3(98, 4, BB), 256, smem>>>(y_hi, y_lo, ww_hi, ww_lo,
        wy, nullptr, nullptr, nullptr, CIn, CCH, sCI, 0LL, (long long)NN * CCH, 0LL);

    // BN stats
    stats_part<<<dim3(4, 98), 128>>>(wy, part);
    stats_fin<<<1, 512>>>(part, stats);

    // transpose + BN affine + residual
    final_kernel<<<dim3(NN / 32, CCH / 32, BB), dim3(32, 8)>>>(wy, x, gamma, beta, stats, out);
}

// round 9
// speedup vs baseline: 1.1169x; 1.1169x over previous
#include <cuda_runtime.h>
#include <cuda_bf16.h>
#include <stdint.h>
#include <math.h>

typedef __nv_bfloat16 bf16;
typedef unsigned int u32;

// ---------------- problem constants ----------------
#define BB 4
#define CCH 512
#define CIn 256
#define NN 12544
#define MMr 1568          // real pooled positions
#define MP_Y 1600         // pad for y-GEMM K (25*64)
#define MP_F 1664         // pad for f-GEMM N (13*128)
#define EPS 1e-5f

// ---------------- scratch layout (byte offsets) ----------------
#define XT_HI    0ULL
#define XT_LO    51380224ULL
#define F_OFF    0ULL
#define CONV_HI  334987264ULL
#define CONV_LO  412057600ULL
#define P_HI     334987264ULL
#define P_LO     495550464ULL
#define Y_HI     0ULL
#define Y_LO     25690112ULL
#define WY_OFF   102760448ULL
#define GT_HI    656113664ULL
#define GT_LO    659390464ULL
#define PHP_HI   662667264ULL
#define PHP_LO   666075136ULL
#define W8_OFF   669483008ULL
#define BCAT_OFF 671580160ULL
#define PART_OFF 671583232ULL
#define SCRATCH_BYTES 672000000ULL

#define CONV_PLANE 25690112ULL   // bytes per conv plane (4*NN*256*2)

__device__ __align__(128) unsigned char d_scratch[SCRATCH_BYTES];
__device__ __align__(16) float d_stats[2 * CCH];

// ---------------- helpers ----------------
__device__ __forceinline__ u32 smem_u32(const void* p) {
    u32 a;
    asm("{ .reg .u64 t; cvta.to.shared.u64 t, %1; cvt.u32.u64 %0, t; }" : "=r"(a) : "l"(p));
    return a;
}
__device__ __forceinline__ void ldsm4(u32& r0, u32& r1, u32& r2, u32& r3, u32 addr) {
    asm volatile("ldmatrix.sync.aligned.m8n8.x4.shared.b16 {%0,%1,%2,%3}, [%4];"
                 : "=r"(r0), "=r"(r1), "=r"(r2), "=r"(r3) : "r"(addr));
}
__device__ __forceinline__ void mma16816(float* d, const u32* a, const u32* b) {
    asm volatile(
        "mma.sync.aligned.m16n8k16.row.col.f32.bf16.bf16.f32 "
        "{%0,%1,%2,%3},{%4,%5,%6,%7},{%8,%9},{%0,%1,%2,%3};"
        : "+f"(d[0]), "+f"(d[1]), "+f"(d[2]), "+f"(d[3])
        : "r"(a[0]), "r"(a[1]), "r"(a[2]), "r"(a[3]), "r"(b[0]), "r"(b[1]));
}
__device__ __forceinline__ u32 sw128(u32 off) { return off ^ ((off >> 3) & 0x70); }
__device__ __forceinline__ void cp16(u32 dst, const void* src) {
    asm volatile("cp.async.cg.shared.global [%0], [%1], 16;" :: "r"(dst), "l"(src));
}
#define CP_COMMIT() asm volatile("cp.async.commit_group;" ::: "memory")
#define CP_WAIT1()  asm volatile("cp.async.wait_group 1;" ::: "memory")

// ---------------- cp.async split-bf16 GEMM (R7-validated core) ----------------
// D = A_hi*B_hi^T + A_hi*B_lo^T + A_lo*B_hi^T  (3 K-passes; A_hi passes adjacent)
// A planes: (Mtot x K) bf16 row-major. B planes: (Ntot x K) bf16 row-major.
// CTA tile 128x128, BK=64, 8 warps (2M x 4N), 3-stage cp.async ring, 2 CTAs/SM.
// EPI 0: fp32 C + optional col bias. EPI 1: bf16 hi/lo planes.
// SEG 1: 256-col segmented output (fused conv).
template <int EPI, int SEG>
__global__ __launch_bounds__(256, 2)
void tgemm(const bf16* __restrict__ Ahi, const bf16* __restrict__ Alo,
           const bf16* __restrict__ Bhi, const bf16* __restrict__ Blo,
           float* __restrict__ Cf, bf16* __restrict__ Chi, bf16* __restrict__ Clo,
           const float* __restrict__ bias,
           int K, int ldc, long long sA, long long sB, long long sC, long long segS)
{
    extern __shared__ __align__(1024) unsigned char sm[];
    const u32 sbase = smem_u32(sm);
    const int tid = threadIdx.x;
    const int wid = tid >> 5;
    const int lane = tid & 31;
    const int m0 = blockIdx.x * 128;
    const int n0 = blockIdx.y * 128;
    const long long bz = blockIdx.z;
    Ahi += bz * sA; Alo += bz * sA;
    Bhi += bz * sB; Blo += bz * sB;

    const int Kc = K >> 6;
    const int total = 3 * Kc;

    // ---- cp.async mapping: thread -> row (tid>>1), 4 x 16B chunks ----
    const int rowL = tid >> 1;
    const int segb = (tid & 1) * 32;     // element offset within 64-elem row
    const long long gA = (long long)(m0 + rowL) * K + segb;
    const long long gB = (long long)(n0 + rowL) * K + segb;
    u32 soff[4];
#pragma unroll
    for (int i = 0; i < 4; i++)
        soff[i] = sw128((u32)rowL * 128 + (u32)segb * 2 + i * 16);

// pass order: 0 = hi*hi, 1 = hi*lo, 2 = lo*hi (A_hi reused in passes 0,1)
#define ISSUE(it2) do { \
    const int _p = (it2) / Kc; \
    const int _k0 = ((it2) - _p * Kc) << 6; \
    const bf16* _A = (_p == 2) ? Alo : Ahi; \
    const bf16* _B = (_p == 1) ? Blo : Bhi; \
    const u32 _sa = sbase + ((it2) % 3) * 32768u; \
    const u32 _sb = _sa + 16384u; \
    _Pragma("unroll") \
    for (int _i = 0; _i < 4; _i++) { \
        cp16(_sa + soff[_i], _A + gA + _k0 + _i * 8); \
        cp16(_sb + soff[_i], _B + gB + _k0 + _i * 8); \
    } \
} while (0)

    // ---- per-lane ldmatrix bases ----
    const int wm = wid >> 2;
    const int wn = wid & 3;
    const int rowA = wm * 64 + ((lane >> 3) & 1) * 8 + (lane & 7);
    const u32 kbA = (u32)(lane >> 4) * 16;
    const int rowB = wn * 32 + ((lane >> 4) & 1) * 8 + (lane & 7);
    const u32 kbB = (u32)((lane >> 3) & 1) * 16;

    float acc[4][4][4];
#pragma unroll
    for (int mt = 0; mt < 4; mt++)
#pragma unroll
        for (int nt = 0; nt < 4; nt++)
#pragma unroll
            for (int q = 0; q < 4; q++) acc[mt][nt][q] = 0.f;

    // prologue: stages 0,1
    ISSUE(0); CP_COMMIT();
    ISSUE(1); CP_COMMIT();

    for (int it = 0; it < total; it++) {
        CP_WAIT1();
        __syncthreads();
        if (it + 2 < total) ISSUE(it + 2);
        CP_COMMIT();

        const u32 sA32 = sbase + (it % 3) * 32768u;
        const u32 sB32 = sA32 + 16384u;
#pragma unroll
        for (int kk = 0; kk < 4; kk++) {
            u32 af[4][4];
#pragma unroll
            for (int mt = 0; mt < 4; mt++) {
                u32 off = (u32)(rowA + mt * 16) * 128 + (u32)kk * 32 + kbA;
                ldsm4(af[mt][0], af[mt][1], af[mt][2], af[mt][3], sA32 + sw128(off));
            }
            u32 bfr[2][4];
#pragma unroll
            for (int nt2 = 0; nt2 < 2; nt2++) {
                u32 off = (u32)(rowB + nt2 * 16) * 128 + (u32)kk * 32 + kbB;
                ldsm4(bfr[nt2][0], bfr[nt2][1], bfr[nt2][2], bfr[nt2][3], sB32 + sw128(off));
            }
#pragma unroll
            for (int mt = 0; mt < 4; mt++)
#pragma unroll
                for (int nt = 0; nt < 4; nt++)
                    mma16816(acc[mt][nt], af[mt], &bfr[nt >> 1][(nt & 1) * 2]);
        }
    }
#undef ISSUE

    // ---- epilogue ----
    const int r0 = m0 + wm * 64 + (lane >> 2);
    const int cb0 = n0 + wn * 32 + (lane & 3) * 2;
    const long long obase = bz * sC + (SEG ? (long long)(n0 >> 8) * segS : 0LL);
#pragma unroll
    for (int nt = 0; nt < 4; nt++) {
        const int c = cb0 + nt * 8;
        const int cl = SEG ? (c & 255) : c;
        const float b0v = bias ? bias[c] : 0.f;
        const float b1v = bias ? bias[c + 1] : 0.f;
#pragma unroll
        for (int mt = 0; mt < 4; mt++) {
            const long long ra = r0 + mt * 16;
            const long long rb = ra + 8;
            float v0 = acc[mt][nt][0] + b0v;
            float v1 = acc[mt][nt][1] + b1v;
            float v2 = acc[mt][nt][2] + b0v;
            float v3 = acc[mt][nt][3] + b1v;
            if (EPI == 0) {
                float* base = Cf + obase;
                *(float2*)(base + ra * ldc + cl) = make_float2(v0, v1);
                *(float2*)(base + rb * ldc + cl) = make_float2(v2, v3);
            } else {
                bf16 h0 = __float2bfloat16(v0), h1 = __float2bfloat16(v1);
                bf16 h2 = __float2bfloat16(v2), h3 = __float2bfloat16(v3);
                bf16 l0 = __float2bfloat16(v0 - __bfloat162float(h0));
                bf16 l1 = __float2bfloat16(v1 - __bfloat162float(h1));
                bf16 l2 = __float2bfloat16(v2 - __bfloat162float(h2));
                bf16 l3 = __float2bfloat16(v3 - __bfloat162float(h3));
                bf16* hb = Chi + obase;
                bf16* lb = Clo + obase;
                *(u32*)(hb + ra * ldc + cl) = (u32)__bfloat16_as_ushort(h0) | ((u32)__bfloat16_as_ushort(h1) << 16);
                *(u32*)(hb + rb * ldc + cl) = (u32)__bfloat16_as_ushort(h2) | ((u32)__bfloat16_as_ushort(h3) << 16);
                *(u32*)(lb + ra * ldc + cl) = (u32)__bfloat16_as_ushort(l0) | ((u32)__bfloat16_as_ushort(l1) << 16);
                *(u32*)(lb + rb * ldc + cl) = (u32)__bfloat16_as_ushort(l2) | ((u32)__bfloat16_as_ushort(l3) << 16);
            }
        }
    }
}

// ---------------- prep: all weight splits + bias concat in one launch ----------------
__global__ void prep_kernel(const float* __restrict__ tw, const float* __restrict__ gw,
                            const float* __restrict__ pw, const float* __restrict__ ww,
                            const float* __restrict__ tb, const float* __restrict__ gb,
                            const float* __restrict__ pb,
                            bf16* __restrict__ wcat_hi, bf16* __restrict__ wcat_lo,
                            bf16* __restrict__ wwhi, bf16* __restrict__ wwlo,
                            float* __restrict__ bcat)
{
    const int i = blockIdx.x * 256 + threadIdx.x;   // grid 2048 -> 524288 threads
    const int t = i >> 17;                          // tensor 0..3
    const int j = i & 131071;
    const float* src = (t == 0) ? tw : (t == 1) ? gw : (t == 2) ? pw : ww;
    const float v = src[j];
    const bf16 h = __float2bfloat16(v);
    const bf16 l = __float2bfloat16(v - __bfloat162float(h));
    if (t < 3) {
        wcat_hi[t * 131072 + j] = h;
        wcat_lo[t * 131072 + j] = l;
    } else {
        wwhi[j] = h;
        wwlo[j] = l;
    }
    if (i < 768) {
        const float* bs = (i < 256) ? tb : (i < 512) ? gb : pb;
        bcat[i] = bs[i & 255];
    }
}

// ---------------- zero fill ----------------
__global__ void zero_kernel(float4* __restrict__ p, long long n4)
{
    long long i = (long long)blockIdx.x * 256 + threadIdx.x;
    const long long stride = (long long)gridDim.x * 256;
    for (; i < n4; i += stride) p[i] = make_float4(0.f, 0.f, 0.f, 0.f);
}

// ---------------- transpose x (b,512,N) -> xT hi/lo (b,N,512) ----------------
__global__ void xpose_kernel(const float* __restrict__ x, bf16* __restrict__ xhi,
                             bf16* __restrict__ xlo)
{
    __shared__ float t[32][33];
    const int b = blockIdx.z;
    const int n0 = blockIdx.x * 32;
    const int c0 = blockIdx.y * 32;
    const int tx = threadIdx.x, ty = threadIdx.y;
    const float* xb = x + (long long)b * CCH * NN;
#pragma unroll
    for (int k = 0; k < 4; k++)
        t[ty + k * 8][tx] = xb[(long long)(c0 + ty + k * 8) * NN + n0 + tx];
    __syncthreads();
    bf16* hb = xhi + (long long)b * NN * CCH;
    bf16* lb = xlo + (long long)b * NN * CCH;
#pragma unroll
    for (int k = 0; k < 4; k++) {
        float v = t[tx][ty + k * 8];
        long long o = (long long)(n0 + ty + k * 8) * CCH + c0 + tx;
        bf16 h = __float2bfloat16(v);
        hb[o] = h;
        lb[o] = __float2bfloat16(v - __bfloat162float(h));
    }
}

// ---------------- 2x2x2 maxpool (from bf16 hi/lo conv planes) + split ----------------
__global__ void pool_kernel(const bf16* __restrict__ gH, const bf16* __restrict__ gL,
                            const bf16* __restrict__ pH, const bf16* __restrict__ pL,
                            bf16* __restrict__ gThi, bf16* __restrict__ gTlo,
                            bf16* __restrict__ phphi, bf16* __restrict__ phplo)
{
    const int m = blockIdx.x;      // 0..1567
    const int b = blockIdx.y;
    const int ci = threadIdx.x;    // 0..255
    const int tp = m / 196;
    const int r = m % 196;
    const int hp = r / 14;
    const int wp = r % 14;
    const long long bb = (long long)b * NN;
    float gm = -1e30f, pm = -1e30f;
#pragma unroll
    for (int dt = 0; dt < 2; dt++)
#pragma unroll
        for (int dh = 0; dh < 2; dh++)
#pragma unroll
            for (int dw = 0; dw < 2; dw++) {
                const long long n = (long long)(2 * tp + dt) * 784 + (2 * hp + dh) * 28 + (2 * wp + dw);
                const long long o = (bb + n) * CIn + ci;
                float gv = __bfloat162float(gH[o]) + __bfloat162float(gL[o]);
                float pv = __bfloat162float(pH[o]) + __bfloat162float(pL[o]);
                gm = fmaxf(gm, gv);
                pm = fmaxf(pm, pv);
            }
    {
        long long o = ((long long)b * MP_F + m) * CIn + ci;
        bf16 h = __float2bfloat16(pm);
        phphi[o] = h;
        phplo[o] = __float2bfloat16(pm - __bfloat162float(h));
    }
    {
        long long o = ((long long)b * CIn + ci) * MP_Y + m;
        bf16 h = __float2bfloat16(gm);
        gThi[o] = h;
        gTlo[o] = __float2bfloat16(gm - __bfloat162float(h));
    }
}

// ---------------- softmax: single global read via smem row cache ----------------
__global__ __launch_bounds__(256)
void softmax_kernel(const float* __restrict__ f, bf16* __restrict__ phi_,
                    bf16* __restrict__ plo_)
{
    __shared__ float row[MMr];
    __shared__ float red[8];
    const long long r = blockIdx.x;
    const float* p = f + r * MP_F;
    bf16* oh = phi_ + r * MP_Y;
    bf16* ol = plo_ + r * MP_Y;
    const int tid = threadIdx.x;
    const int wid = tid >> 5, lane = tid & 31;

    float mx = -1e30f;
    for (int i = tid; i < MMr; i += 256) {
        float v = p[i];
        row[i] = v;
        mx = fmaxf(mx, v);
    }
#pragma unroll
    for (int s = 16; s > 0; s >>= 1) mx = fmaxf(mx, __shfl_xor_sync(~0u, mx, s));
    if (lane == 0) red[wid] = mx;
    __syncthreads();
    {
        float t = red[lane & 7];
#pragma unroll
        for (int s = 4; s > 0; s >>= 1) t = fmaxf(t, __shfl_xor_sync(~0u, t, s));
        mx = t;
    }

    float sum = 0.f;
    for (int i = tid; i < MMr; i += 256) {
        float e = __expf(row[i] - mx);
        row[i] = e;
        sum += e;
    }
#pragma unroll
    for (int s = 16; s > 0; s >>= 1) sum += __shfl_xor_sync(~0u, sum, s);
    __syncthreads();
    if (lane == 0) red[wid] = sum;
    __syncthreads();
    {
        float t = red[lane & 7];
#pragma unroll
        for (int s = 4; s > 0; s >>= 1) t += __shfl_xor_sync(~0u, t, s);
        sum = t;
    }
    const float inv = 1.f / sum;

    for (int i = tid; i < MMr; i += 256) {
        float v = row[i] * inv;
        bf16 h = __float2bfloat16(v);
        oh[i] = h;
        ol[i] = __float2bfloat16(v - __bfloat162float(h));
    }
    if (tid < MP_Y - MMr) {
        oh[MMr + tid] = __ushort_as_bfloat16(0);
        ol[MMr + tid] = __ushort_as_bfloat16(0);
    }
}

// ---------------- BN stats: partial sums then finalize ----------------
__global__ void stats_part(const float* __restrict__ wy, float* __restrict__ part)
{
    const int c = blockIdx.x * 128 + threadIdx.x;
    const int rb = blockIdx.y;                      // 98 row blocks of 512 rows
    const float* p = wy + (long long)rb * 512 * CCH + c;
    float s = 0.f, ss = 0.f;
    for (int r = 0; r < 512; r++) {
        float v = p[(long long)r * CCH];
        s += v;
        ss += v * v;
    }
    part[(long long)rb * 1024 + c] = s;
    part[(long long)rb * 1024 + 512 + c] = ss;
}

__global__ void stats_fin(const float* __restrict__ part, float* __restrict__ stats)
{
    const int c = threadIdx.x;   // 512
    float s = 0.f, ss = 0.f;
    for (int r = 0; r < 98; r++) {
        s += part[r * 1024 + c];
        ss += part[r * 1024 + 512 + c];
    }
    const float cnt = (float)BB * (float)NN;
    const float mean = s / cnt;
    const float var = ss / cnt - mean * mean;
    stats[c] = mean;
    stats[CCH + c] = rsqrtf(var + EPS);
}

// ---------------- final: transpose wy (b,n,c)->(b,c,n), BN affine + residual ----------------
__global__ void final_kernel(const float* __restrict__ wy, const float* __restrict__ x,
                             const float* __restrict__ gamma, const float* __restrict__ beta,
                             const float* __restrict__ stats, float* __restrict__ out)
{
    __shared__ float t[32][33];
    const int b = blockIdx.z;
    const int n0 = blockIdx.x * 32;
    const int c0 = blockIdx.y * 32;
    const int tx = threadIdx.x, ty = threadIdx.y;
    const float* wb = wy + (long long)b * NN * CCH;
#pragma unroll
    for (int k = 0; k < 4; k++)
        t[ty + k * 8][tx] = wb[(long long)(n0 + ty + k * 8) * CCH + c0 + tx];
    __syncthreads();
#pragma unroll
    for (int k = 0; k < 4; k++) {
        const int c = c0 + ty + k * 8;
        const float mean = stats[c];
        const float rstd = stats[CCH + c];
        const float gs = gamma[c] * rstd;
        const float off = beta[c] - mean * gs;
        const long long o = ((long long)b * CCH + c) * NN + n0 + tx;
        out[o] = t[tx][ty + k * 8] * gs + off + x[o];
    }
}

// ---------------- launch ----------------
extern "C" void kernel_launch(void* const* d_in, const int* in_sizes, int n_in,
                              void* d_out, int out_size)
{
    const float* x       = (const float*)d_in[0];
    const float* g_w     = (const float*)d_in[1];
    const float* g_b     = (const float*)d_in[2];
    const float* theta_w = (const float*)d_in[3];
    const float* theta_b = (const float*)d_in[4];
    const float* phi_w   = (const float*)d_in[5];
    const float* phi_b   = (const float*)d_in[6];
    const float* W_w     = (const float*)d_in[7];
    // d_in[8] = W_b: constant channel bias cancels exactly in training-mode BN — skipped.
    const float* gamma   = (const float*)d_in[9];
    const float* beta    = (const float*)d_in[10];
    float* out = (float*)d_out;

    unsigned char* S = nullptr;
    float* stats = nullptr;
    cudaGetSymbolAddress((void**)&S, d_scratch);
    cudaGetSymbolAddress((void**)&stats, d_stats);

    bf16* xt_hi  = (bf16*)(S + XT_HI);
    bf16* xt_lo  = (bf16*)(S + XT_LO);
    float* f     = (float*)(S + F_OFF);
    bf16* conv_hi = (bf16*)(S + CONV_HI);   // [theta | g | phi] planes, each (b,n,256)
    bf16* conv_lo = (bf16*)(S + CONV_LO);
    bf16* th_hi  = conv_hi;                 // seg 0
    bf16* th_lo  = conv_lo;
    bf16* gc_hi  = (bf16*)(S + CONV_HI + CONV_PLANE);       // seg 1
    bf16* gc_lo  = (bf16*)(S + CONV_LO + CONV_PLANE);
    bf16* pc_hi  = (bf16*)(S + CONV_HI + 2 * CONV_PLANE);   // seg 2
    bf16* pc_lo  = (bf16*)(S + CONV_LO + 2 * CONV_PLANE);
    bf16* p_hi   = (bf16*)(S + P_HI);
    bf16* p_lo   = (bf16*)(S + P_LO);
    bf16* y_hi   = (bf16*)(S + Y_HI);
    bf16* y_lo   = (bf16*)(S + Y_LO);
    float* wy    = (float*)(S + WY_OFF);
    bf16* gt_hi  = (bf16*)(S + GT_HI);
    bf16* gt_lo  = (bf16*)(S + GT_LO);
    bf16* php_hi = (bf16*)(S + PHP_HI);
    bf16* php_lo = (bf16*)(S + PHP_LO);
    bf16* wcat_hi = (bf16*)(S + W8_OFF);                    // 768 x 512
    bf16* wcat_lo = (bf16*)(S + W8_OFF + 786432);
    bf16* ww_hi  = (bf16*)(S + W8_OFF + 1572864);           // 512 x 256
    bf16* ww_lo  = (bf16*)(S + W8_OFF + 1835008);
    float* bcat  = (float*)(S + BCAT_OFF);                  // 768
    float* part  = (float*)(S + PART_OFF);

    const int smem = 3 * 32768;   // 96 KB: 3-stage ring
    cudaFuncSetAttribute(tgemm<0, 0>, cudaFuncAttributeMaxDynamicSharedMemorySize, smem);
    cudaFuncSetAttribute(tgemm<1, 0>, cudaFuncAttributeMaxDynamicSharedMemorySize, smem);
    cudaFuncSetAttribute(tgemm<1, 1>, cudaFuncAttributeMaxDynamicSharedMemorySize, smem);

    const long long sXT = (long long)NN * CCH;
    const long long sCI = (long long)NN * CIn;

    // launch 0: weight splits + bias concat
    prep_kernel<<<2048, 256>>>(theta_w, g_w, phi_w, W_w, theta_b, g_b, phi_b,
                               wcat_hi, wcat_lo, ww_hi, ww_lo, bcat);

    // launch 1: zero gt/php pad region (13,369,344 B contiguous at GT_HI)
    zero_kernel<<<2048, 256>>>((float4*)(S + GT_HI), 13369344 / 16);

    // launch 2: transpose + split x -> xT (b, n, 512)
    xpose_kernel<<<dim3(NN / 32, CCH / 32, BB), dim3(32, 8)>>>(x, xt_hi, xt_lo);

    // launch 3: fused conv [theta|g|phi] = xT @ wcat^T -> bf16 hi/lo planes
    tgemm<1, 1><<<dim3(98, 6, BB), 256, smem>>>(xt_hi, xt_lo, wcat_hi, wcat_lo,
        nullptr, conv_hi, conv_lo, bcat, CCH, CIn, sXT, 0LL, sCI, 4LL * sCI);

    // launch 4: pool + split: gT (b,256,1600), php (b,1664,256)
    pool_kernel<<<dim3(MMr, BB), 256>>>(gc_hi, gc_lo, pc_hi, pc_lo,
                                        gt_hi, gt_lo, php_hi, php_lo);

    // launch 5 (ncu-profiled): f = theta @ phi^T : (b, n, 1664) fp32
    tgemm<0, 0><<<dim3(98, MP_F / 128, BB), 256, smem>>>(th_hi, th_lo, php_hi, php_lo,
        f, nullptr, nullptr, nullptr, CIn, MP_F, sCI, (long long)MP_F * CIn,
        (long long)NN * MP_F, 0LL);

    // launch 6: softmax -> p hi/lo (b, n, 1600)
    softmax_kernel<<<BB * NN, 256>>>(f, p_hi, p_lo);

    // launch 7: y = p @ gT^T : (b, n, 256) bf16 planes
    tgemm<1, 0><<<dim3(98, 2, BB), 256, smem>>>(p_hi, p_lo, gt_hi, gt_lo,
        nullptr, y_hi, y_lo, nullptr, MP_Y, CIn, (long long)NN * MP_Y,
        (long long)CIn * MP_Y, sCI, 0LL);

    // launch 8: wy = y @ W_w^T : (b, n, 512) fp32  (W_b cancels in BN)
    tgemm<0, 0><<<dim3(98, 4, BB), 256, smem>>>(y_hi, y_lo, ww_hi, ww_lo,
        wy, nullptr, nullptr, nullptr, CIn, CCH, sCI, 0LL, (long long)NN * CCH, 0LL);

    // launches 9-10: BN stats
    stats_part<<<dim3(4, 98), 128>>>(wy, part);
    stats_fin<<<1, 512>>>(part, stats);

    // launch 11: transpose + BN affine + residual
    final_kernel<<<dim3(NN / 32, CCH / 32, BB), dim3(32, 8)>>>(wy, x, gamma, beta, stats, out);
}

// round 11
// speedup vs baseline: 1.2354x; 1.1061x over previous
#include <cuda_runtime.h>
#include <cuda_bf16.h>
#include <cuda_fp16.h>
#include <stdint.h>
#include <math.h>

typedef __nv_bfloat16 bf16;
typedef unsigned int u32;

// ---------------- problem constants ----------------
#define BB 4
#define CCH 512
#define CIn 256
#define NN 12544
#define MMr 1568          // real pooled positions
#define MP_Y 1600         // pad for y-GEMM K (25*64)
#define MP_F 1664         // pad for f-GEMM N (13*128)
#define EPS 1e-5f

// ---------------- scratch layout (byte offsets) ----------------
#define XT_HI    0ULL
#define XT_LO    51380224ULL
#define F_OFF    0ULL
#define CONV_HI  334987264ULL
#define CONV_LO  412057600ULL
#define P_F16    334987264ULL   // aliases conv planes (dead after f GEMM reads theta, pool reads g/phi)
#define Y_HI     0ULL
#define Y_LO     25690112ULL
#define WY_OFF   102760448ULL
#define GT_HI    656113664ULL
#define GT_LO    659390464ULL
#define PHP_HI   662667264ULL
#define PHP_LO   666075136ULL
#define W8_OFF   669483008ULL
#define BCAT_OFF 671580160ULL
#define PART_OFF 671583232ULL
#define SCRATCH_BYTES 672000000ULL

#define CONV_PLANE 25690112ULL   // bytes per conv plane (4*NN*256*2)

__device__ __align__(128) unsigned char d_scratch[SCRATCH_BYTES];
__device__ __align__(16) float d_stats[2 * CCH];

// ---------------- helpers ----------------
__device__ __forceinline__ u32 smem_u32(const void* p) {
    u32 a;
    asm("{ .reg .u64 t; cvta.to.shared.u64 t, %1; cvt.u32.u64 %0, t; }" : "=r"(a) : "l"(p));
    return a;
}
__device__ __forceinline__ void ldsm4(u32& r0, u32& r1, u32& r2, u32& r3, u32 addr) {
    asm volatile("ldmatrix.sync.aligned.m8n8.x4.shared.b16 {%0,%1,%2,%3}, [%4];"
                 : "=r"(r0), "=r"(r1), "=r"(r2), "=r"(r3) : "r"(addr));
}
template <int F16>
__device__ __forceinline__ void mma16816(float* d, const u32* a, const u32* b) {
    if (F16)
        asm volatile(
            "mma.sync.aligned.m16n8k16.row.col.f32.f16.f16.f32 "
            "{%0,%1,%2,%3},{%4,%5,%6,%7},{%8,%9},{%0,%1,%2,%3};"
            : "+f"(d[0]), "+f"(d[1]), "+f"(d[2]), "+f"(d[3])
            : "r"(a[0]), "r"(a[1]), "r"(a[2]), "r"(a[3]), "r"(b[0]), "r"(b[1]));
    else
        asm volatile(
            "mma.sync.aligned.m16n8k16.row.col.f32.bf16.bf16.f32 "
            "{%0,%1,%2,%3},{%4,%5,%6,%7},{%8,%9},{%0,%1,%2,%3};"
            : "+f"(d[0]), "+f"(d[1]), "+f"(d[2]), "+f"(d[3])
            : "r"(a[0]), "r"(a[1]), "r"(a[2]), "r"(a[3]), "r"(b[0]), "r"(b[1]));
}
__device__ __forceinline__ u32 sw128(u32 off) { return off ^ ((off >> 3) & 0x70); }
__device__ __forceinline__ void cp16(u32 dst, const void* src) {
    asm volatile("cp.async.cg.shared.global [%0], [%1], 16;" :: "r"(dst), "l"(src));
}
#define CP_COMMIT() asm volatile("cp.async.commit_group;" ::: "memory")
#define CP_WAIT1()  asm volatile("cp.async.wait_group 1;" ::: "memory")

// ---------------- cp.async split 16-bit GEMM (R7-validated core) ----------------
// Passes: 0 = A_hi*B_hi^T, 1 = A_hi*B_lo^T, 2 = A_lo*B_hi^T.
// NP=3: full 3-term split (bf16). NP=2: A_hi*(B_hi+B_lo) (fp16 softmax path).
// A planes: (Mtot x K) 16-bit row-major. B planes: (Ntot x K) 16-bit row-major.
// CTA tile 128x128, BK=64, 8 warps (2M x 4N), 3-stage cp.async ring, 2 CTAs/SM.
// EPI 0: fp32 C + optional col bias. EPI 1: bf16 hi/lo planes.
// SEG 1: 256-col segmented output (fused conv). F16: fp16 mma instead of bf16.
template <int EPI, int SEG, int NP, int F16>
__global__ __launch_bounds__(256, 2)
void tgemm(const bf16* __restrict__ Ahi, const bf16* __restrict__ Alo,
           const bf16* __restrict__ Bhi, const bf16* __restrict__ Blo,
           float* __restrict__ Cf, bf16* __restrict__ Chi, bf16* __restrict__ Clo,
           const float* __restrict__ bias,
           int K, int ldc, long long sA, long long sB, long long sC, long long segS)
{
    extern __shared__ __align__(1024) unsigned char sm[];
    const u32 sbase = smem_u32(sm);
    const int tid = threadIdx.x;
    const int wid = tid >> 5;
    const int lane = tid & 31;
    const int m0 = blockIdx.x * 128;
    const int n0 = blockIdx.y * 128;
    const long long bz = blockIdx.z;
    Ahi += bz * sA; Alo += bz * sA;
    Bhi += bz * sB; Blo += bz * sB;

    const int Kc = K >> 6;
    const int total = NP * Kc;

    // ---- cp.async mapping: thread -> row (tid>>1), 4 x 16B chunks ----
    const int rowL = tid >> 1;
    const int segb = (tid & 1) * 32;     // element offset within 64-elem row
    const long long gA = (long long)(m0 + rowL) * K + segb;
    const long long gB = (long long)(n0 + rowL) * K + segb;
    u32 soff[4];
#pragma unroll
    for (int i = 0; i < 4; i++)
        soff[i] = sw128((u32)rowL * 128 + (u32)segb * 2 + i * 16);

// pass order: 0 = hi*hi, 1 = hi*lo, 2 = lo*hi (A_hi reused in passes 0,1)
#define ISSUE(it2) do { \
    const int _p = (it2) / Kc; \
    const int _k0 = ((it2) - _p * Kc) << 6; \
    const bf16* _A = (_p == 2) ? Alo : Ahi; \
    const bf16* _B = (_p == 1) ? Blo : Bhi; \
    const u32 _sa = sbase + ((it2) % 3) * 32768u; \
    const u32 _sb = _sa + 16384u; \
    _Pragma("unroll") \
    for (int _i = 0; _i < 4; _i++) { \
        cp16(_sa + soff[_i], _A + gA + _k0 + _i * 8); \
        cp16(_sb + soff[_i], _B + gB + _k0 + _i * 8); \
    } \
} while (0)

    // ---- per-lane ldmatrix bases ----
    const int wm = wid >> 2;
    const int wn = wid & 3;
    const int rowA = wm * 64 + ((lane >> 3) & 1) * 8 + (lane & 7);
    const u32 kbA = (u32)(lane >> 4) * 16;
    const int rowB = wn * 32 + ((lane >> 4) & 1) * 8 + (lane & 7);
    const u32 kbB = (u32)((lane >> 3) & 1) * 16;

    float acc[4][4][4];
#pragma unroll
    for (int mt = 0; mt < 4; mt++)
#pragma unroll
        for (int nt = 0; nt < 4; nt++)
#pragma unroll
            for (int q = 0; q < 4; q++) acc[mt][nt][q] = 0.f;

    // prologue: stages 0,1
    ISSUE(0); CP_COMMIT();
    ISSUE(1); CP_COMMIT();

    for (int it = 0; it < total; it++) {
        CP_WAIT1();
        __syncthreads();
        if (it + 2 < total) ISSUE(it + 2);
        CP_COMMIT();

        const u32 sA32 = sbase + (it % 3) * 32768u;
        const u32 sB32 = sA32 + 16384u;
#pragma unroll
        for (int kk = 0; kk < 4; kk++) {
            u32 af[4][4];
#pragma unroll
            for (int mt = 0; mt < 4; mt++) {
                u32 off = (u32)(rowA + mt * 16) * 128 + (u32)kk * 32 + kbA;
                ldsm4(af[mt][0], af[mt][1], af[mt][2], af[mt][3], sA32 + sw128(off));
            }
            u32 bfr[2][4];
#pragma unroll
            for (int nt2 = 0; nt2 < 2; nt2++) {
                u32 off = (u32)(rowB + nt2 * 16) * 128 + (u32)kk * 32 + kbB;
                ldsm4(bfr[nt2][0], bfr[nt2][1], bfr[nt2][2], bfr[nt2][3], sB32 + sw128(off));
            }
#pragma unroll
            for (int mt = 0; mt < 4; mt++)
#pragma unroll
                for (int nt = 0; nt < 4; nt++)
                    mma16816<F16>(acc[mt][nt], af[mt], &bfr[nt >> 1][(nt & 1) * 2]);
        }
    }
#undef ISSUE

    // ---- epilogue ----
    const int r0 = m0 + wm * 64 + (lane >> 2);
    const int cb0 = n0 + wn * 32 + (lane & 3) * 2;
    const long long obase = bz * sC + (SEG ? (long long)(n0 >> 8) * segS : 0LL);
#pragma unroll
    for (int nt = 0; nt < 4; nt++) {
        const int c = cb0 + nt * 8;
        const int cl = SEG ? (c & 255) : c;
        const float b0v = bias ? bias[c] : 0.f;
        const float b1v = bias ? bias[c + 1] : 0.f;
#pragma unroll
        for (int mt = 0; mt < 4; mt++) {
            const long long ra = r0 + mt * 16;
            const long long rb = ra + 8;
            float v0 = acc[mt][nt][0] + b0v;
            float v1 = acc[mt][nt][1] + b1v;
            float v2 = acc[mt][nt][2] + b0v;
            float v3 = acc[mt][nt][3] + b1v;
            if (EPI == 0) {
                float* base = Cf + obase;
                *(float2*)(base + ra * ldc + cl) = make_float2(v0, v1);
                *(float2*)(base + rb * ldc + cl) = make_float2(v2, v3);
            } else {
                bf16 h0 = __float2bfloat16(v0), h1 = __float2bfloat16(v1);
                bf16 h2 = __float2bfloat16(v2), h3 = __float2bfloat16(v3);
                bf16 l0 = __float2bfloat16(v0 - __bfloat162float(h0));
                bf16 l1 = __float2bfloat16(v1 - __bfloat162float(h1));
                bf16 l2 = __float2bfloat16(v2 - __bfloat162float(h2));
                bf16 l3 = __float2bfloat16(v3 - __bfloat162float(h3));
                bf16* hb = Chi + obase;
                bf16* lb = Clo + obase;
                *(u32*)(hb + ra * ldc + cl) = (u32)__bfloat16_as_ushort(h0) | ((u32)__bfloat16_as_ushort(h1) << 16);
                *(u32*)(hb + rb * ldc + cl) = (u32)__bfloat16_as_ushort(h2) | ((u32)__bfloat16_as_ushort(h3) << 16);
                *(u32*)(lb + ra * ldc + cl) = (u32)__bfloat16_as_ushort(l0) | ((u32)__bfloat16_as_ushort(l1) << 16);
                *(u32*)(lb + rb * ldc + cl) = (u32)__bfloat16_as_ushort(l2) | ((u32)__bfloat16_as_ushort(l3) << 16);
            }
        }
    }
}

// ---------------- prep: all weight splits + bias concat in one launch ----------------
__global__ void prep_kernel(const float* __restrict__ tw, const float* __restrict__ gw,
                            const float* __restrict__ pw, const float* __restrict__ ww,
                            const float* __restrict__ tb, const float* __restrict__ gb,
                            const float* __restrict__ pb,
                            bf16* __restrict__ wcat_hi, bf16* __restrict__ wcat_lo,
                            bf16* __restrict__ wwhi, bf16* __restrict__ wwlo,
                            float* __restrict__ bcat)
{
    const int i = blockIdx.x * 256 + threadIdx.x;   // grid 2048 -> 524288 threads
    const int t = i >> 17;                          // tensor 0..3
    const int j = i & 131071;
    const float* src = (t == 0) ? tw : (t == 1) ? gw : (t == 2) ? pw : ww;
    const float v = src[j];
    const bf16 h = __float2bfloat16(v);
    const bf16 l = __float2bfloat16(v - __bfloat162float(h));
    if (t < 3) {
        wcat_hi[t * 131072 + j] = h;
        wcat_lo[t * 131072 + j] = l;
    } else {
        wwhi[j] = h;
        wwlo[j] = l;
    }
    if (i < 768) {
        const float* bs = (i < 256) ? tb : (i < 512) ? gb : pb;
        bcat[i] = bs[i & 255];
    }
}

// ---------------- zero fill ----------------
__global__ void zero_kernel(float4* __restrict__ p, long long n4)
{
    long long i = (long long)blockIdx.x * 256 + threadIdx.x;
    const long long stride = (long long)gridDim.x * 256;
    for (; i < n4; i += stride) p[i] = make_float4(0.f, 0.f, 0.f, 0.f);
}

// ---------------- transpose x (b,512,N) -> xT hi/lo (b,N,512) ----------------
__global__ void xpose_kernel(const float* __restrict__ x, bf16* __restrict__ xhi,
                             bf16* __restrict__ xlo)
{
    __shared__ float t[32][33];
    const int b = blockIdx.z;
    const int n0 = blockIdx.x * 32;
    const int c0 = blockIdx.y * 32;
    const int tx = threadIdx.x, ty = threadIdx.y;
    const float* xb = x + (long long)b * CCH * NN;
#pragma unroll
    for (int k = 0; k < 4; k++)
        t[ty + k * 8][tx] = xb[(long long)(c0 + ty + k * 8) * NN + n0 + tx];
    __syncthreads();
    bf16* hb = xhi + (long long)b * NN * CCH;
    bf16* lb = xlo + (long long)b * NN * CCH;
#pragma unroll
    for (int k = 0; k < 4; k++) {
        float v = t[tx][ty + k * 8];
        long long o = (long long)(n0 + ty + k * 8) * CCH + c0 + tx;
        bf16 h = __float2bfloat16(v);
        hb[o] = h;
        lb[o] = __float2bfloat16(v - __bfloat162float(h));
    }
}

// ---------------- 2x2x2 maxpool + split; gT -> fp16 hi/lo, php -> bf16 hi/lo ----------------
__global__ void pool_kernel(const bf16* __restrict__ gH, const bf16* __restrict__ gL,
                            const bf16* __restrict__ pH, const bf16* __restrict__ pL,
                            __half* __restrict__ gThi, __half* __restrict__ gTlo,
                            bf16* __restrict__ phphi, bf16* __restrict__ phplo)
{
    const int m = blockIdx.x;      // 0..1567
    const int b = blockIdx.y;
    const int ci = threadIdx.x;    // 0..255
    const int tp = m / 196;
    const int r = m % 196;
    const int hp = r / 14;
    const int wp = r % 14;
    const long long bb = (long long)b * NN;
    float gm = -1e30f, pm = -1e30f;
#pragma unroll
    for (int dt = 0; dt < 2; dt++)
#pragma unroll
        for (int dh = 0; dh < 2; dh++)
#pragma unroll
            for (int dw = 0; dw < 2; dw++) {
                const long long n = (long long)(2 * tp + dt) * 784 + (2 * hp + dh) * 28 + (2 * wp + dw);
                const long long o = (bb + n) * CIn + ci;
                float gv = __bfloat162float(gH[o]) + __bfloat162float(gL[o]);
                float pv = __bfloat162float(pH[o]) + __bfloat162float(pL[o]);
                gm = fmaxf(gm, gv);
                pm = fmaxf(pm, pv);
            }
    {
        long long o = ((long long)b * MP_F + m) * CIn + ci;
        bf16 h = __float2bfloat16(pm);
        phphi[o] = h;
        phplo[o] = __float2bfloat16(pm - __bfloat162float(h));
    }
    {
        long long o = ((long long)b * CIn + ci) * MP_Y + m;
        __half h = __float2half(gm);
        gThi[o] = h;
        gTlo[o] = __float2half(gm - __half2float(h));
    }
}

// ---------------- softmax: single global read; writes p as one fp16 plane ----------------
__global__ __launch_bounds__(256)
void softmax_kernel(const float* __restrict__ f, __half* __restrict__ pout)
{
    __shared__ float row[MMr];
    __shared__ float red[8];
    const long long r = blockIdx.x;
    const float* p = f + r * MP_F;
    __half* oh = pout + r * MP_Y;
    const int tid = threadIdx.x;
    const int wid = tid >> 5, lane = tid & 31;

    float mx = -1e30f;
    for (int i = tid; i < MMr; i += 256) {
        float v = p[i];
        row[i] = v;
        mx = fmaxf(mx, v);
    }
#pragma unroll
    for (int s = 16; s > 0; s >>= 1) mx = fmaxf(mx, __shfl_xor_sync(~0u, mx, s));
    if (lane == 0) red[wid] = mx;
    __syncthreads();
    {
        float t = red[lane & 7];
#pragma unroll
        for (int s = 4; s > 0; s >>= 1) t = fmaxf(t, __shfl_xor_sync(~0u, t, s));
        mx = t;
    }

    float sum = 0.f;
    for (int i = tid; i < MMr; i += 256) {
        float e = __expf(row[i] - mx);
        row[i] = e;
        sum += e;
    }
#pragma unroll
    for (int s = 16; s > 0; s >>= 1) sum += __shfl_xor_sync(~0u, sum, s);
    __syncthreads();
    if (lane == 0) red[wid] = sum;
    __syncthreads();
    {
        float t = red[lane & 7];
#pragma unroll
        for (int s = 4; s > 0; s >>= 1) t += __shfl_xor_sync(~0u, t, s);
        sum = t;
    }
    const float inv = 1.f / sum;

    for (int i = tid; i < MMr; i += 256)
        oh[i] = __float2half(row[i] * inv);
    if (tid < MP_Y - MMr)
        oh[MMr + tid] = __ushort_as_half(0);
}

// ---------------- BN stats: partial sums then finalize ----------------
__global__ void stats_part(const float* __restrict__ wy, float* __restrict__ part)
{
    const int c = blockIdx.x * 128 + threadIdx.x;
    const int rb = blockIdx.y;                      // 98 row blocks of 512 rows
    const float* p = wy + (long long)rb * 512 * CCH + c;
    float s = 0.f, ss = 0.f;
    for (int r = 0; r < 512; r++) {
        float v = p[(long long)r * CCH];
        s += v;
        ss += v * v;
    }
    part[(long long)rb * 1024 + c] = s;
    part[(long long)rb * 1024 + 512 + c] = ss;
}

__global__ void stats_fin(const float* __restrict__ part, float* __restrict__ stats)
{
    const int c = threadIdx.x;   // 512
    float s = 0.f, ss = 0.f;
    for (int r = 0; r < 98; r++) {
        s += part[r * 1024 + c];
        ss += part[r * 1024 + 512 + c];
    }
    const float cnt = (float)BB * (float)NN;
    const float mean = s / cnt;
    const float var = ss / cnt - mean * mean;
    stats[c] = mean;
    stats[CCH + c] = rsqrtf(var + EPS);
}

// ---------------- final: transpose wy (b,n,c)->(b,c,n), BN affine + residual ----------------
__global__ void final_kernel(const float* __restrict__ wy, const float* __restrict__ x,
                             const float* __restrict__ gamma, const float* __restrict__ beta,
                             const float* __restrict__ stats, float* __restrict__ out)
{
    __shared__ float t[32][33];
    const int b = blockIdx.z;
    const int n0 = blockIdx.x * 32;
    const int c0 = blockIdx.y * 32;
    const int tx = threadIdx.x, ty = threadIdx.y;
    const float* wb = wy + (long long)b * NN * CCH;
#pragma unroll
    for (int k = 0; k < 4; k++)
        t[ty + k * 8][tx] = wb[(long long)(n0 + ty + k * 8) * CCH + c0 + tx];
    __syncthreads();
#pragma unroll
    for (int k = 0; k < 4; k++) {
        const int c = c0 + ty + k * 8;
        const float mean = stats[c];
        const float rstd = stats[CCH + c];
        const float gs = gamma[c] * rstd;
        const float off = beta[c] - mean * gs;
        const long long o = ((long long)b * CCH + c) * NN + n0 + tx;
        out[o] = t[tx][ty + k * 8] * gs + off + x[o];
    }
}

// ---------------- launch ----------------
extern "C" void kernel_launch(void* const* d_in, const int* in_sizes, int n_in,
                              void* d_out, int out_size)
{
    const float* x       = (const float*)d_in[0];
    const float* g_w     = (const float*)d_in[1];
    const float* g_b     = (const float*)d_in[2];
    const float* theta_w = (const float*)d_in[3];
    const float* theta_b = (const float*)d_in[4];
    const float* phi_w   = (const float*)d_in[5];
    const float* phi_b   = (const float*)d_in[6];
    const float* W_w     = (const float*)d_in[7];
    // d_in[8] = W_b: constant channel bias cancels exactly in training-mode BN — skipped.
    const float* gamma   = (const float*)d_in[9];
    const float* beta    = (const float*)d_in[10];
    float* out = (float*)d_out;

    unsigned char* S = nullptr;
    float* stats = nullptr;
    cudaGetSymbolAddress((void**)&S, d_scratch);
    cudaGetSymbolAddress((void**)&stats, d_stats);

    bf16* xt_hi  = (bf16*)(S + XT_HI);
    bf16* xt_lo  = (bf16*)(S + XT_LO);
    float* f     = (float*)(S + F_OFF);
    bf16* conv_hi = (bf16*)(S + CONV_HI);   // [theta | g | phi] planes, each (b,n,256)
    bf16* conv_lo = (bf16*)(S + CONV_LO);
    bf16* th_hi  = conv_hi;                 // seg 0
    bf16* th_lo  = conv_lo;
    bf16* gc_hi  = (bf16*)(S + CONV_HI + CONV_PLANE);       // seg 1
    bf16* gc_lo  = (bf16*)(S + CONV_LO + CONV_PLANE);
    bf16* pc_hi  = (bf16*)(S + CONV_HI + 2 * CONV_PLANE);   // seg 2
    bf16* pc_lo  = (bf16*)(S + CONV_LO + 2 * CONV_PLANE);
    __half* p16  = (__half*)(S + P_F16);                    // (b, n, 1600) fp16
    bf16* y_hi   = (bf16*)(S + Y_HI);
    bf16* y_lo   = (bf16*)(S + Y_LO);
    float* wy    = (float*)(S + WY_OFF);
    __half* gt_hi = (__half*)(S + GT_HI);                   // (b, 256, 1600) fp16
    __half* gt_lo = (__half*)(S + GT_LO);
    bf16* php_hi = (bf16*)(S + PHP_HI);
    bf16* php_lo = (bf16*)(S + PHP_LO);
    bf16* wcat_hi = (bf16*)(S + W8_OFF);                    // 768 x 512
    bf16* wcat_lo = (bf16*)(S + W8_OFF + 786432);
    bf16* ww_hi  = (bf16*)(S + W8_OFF + 1572864);           // 512 x 256
    bf16* ww_lo  = (bf16*)(S + W8_OFF + 1835008);
    float* bcat  = (float*)(S + BCAT_OFF);                  // 768
    float* part  = (float*)(S + PART_OFF);

    const int smem = 3 * 32768;   // 96 KB: 3-stage ring
    cudaFuncSetAttribute(tgemm<0, 0, 3, 0>, cudaFuncAttributeMaxDynamicSharedMemorySize, smem);
    cudaFuncSetAttribute(tgemm<1, 0, 2, 1>, cudaFuncAttributeMaxDynamicSharedMemorySize, smem);
    cudaFuncSetAttribute(tgemm<1, 1, 3, 0>, cudaFuncAttributeMaxDynamicSharedMemorySize, smem);

    const long long sXT = (long long)NN * CCH;
    const long long sCI = (long long)NN * CIn;

    // launch 0: weight splits + bias concat
    prep_kernel<<<2048, 256>>>(theta_w, g_w, phi_w, W_w, theta_b, g_b, phi_b,
                               wcat_hi, wcat_lo, ww_hi, ww_lo, bcat);

    // launch 1: zero gt/php pad region (13,369,344 B contiguous at GT_HI)
    zero_kernel<<<2048, 256>>>((float4*)(S + GT_HI), 13369344 / 16);

    // launch 2: transpose + split x -> xT (b, n, 512)
    xpose_kernel<<<dim3(NN / 32, CCH / 32, BB), dim3(32, 8)>>>(x, xt_hi, xt_lo);

    // launch 3: fused conv [theta|g|phi] = xT @ wcat^T -> bf16 hi/lo planes
    tgemm<1, 1, 3, 0><<<dim3(98, 6, BB), 256, smem>>>(xt_hi, xt_lo, wcat_hi, wcat_lo,
        nullptr, conv_hi, conv_lo, bcat, CCH, CIn, sXT, 0LL, sCI, 4LL * sCI);

    // launch 4: pool + split: gT fp16 (b,256,1600), php bf16 (b,1664,256)
    pool_kernel<<<dim3(MMr, BB), 256>>>(gc_hi, gc_lo, pc_hi, pc_lo,
                                        gt_hi, gt_lo, php_hi, php_lo);

    // launch 5 (ncu-profiled): f = theta @ phi^T : (b, n, 1664) fp32, 3-pass bf16
    tgemm<0, 0, 3, 0><<<dim3(98, MP_F / 128, BB), 256, smem>>>(th_hi, th_lo, php_hi, php_lo,
        f, nullptr, nullptr, nullptr, CIn, MP_F, sCI, (long long)MP_F * CIn,
        (long long)NN * MP_F, 0LL);

    // launch 6: softmax -> p fp16 single plane (b, n, 1600)
    softmax_kernel<<<BB * NN, 256>>>(f, p16);

    // launch 7: y = p @ (g_hi + g_lo)^T : 2-pass fp16 mma
    tgemm<1, 0, 2, 1><<<dim3(98, 2, BB), 256, smem>>>(
        (const bf16*)p16, (const bf16*)p16, (const bf16*)gt_hi, (const bf16*)gt_lo,
        nullptr, y_hi, y_lo, nullptr, MP_Y, CIn, (long long)NN * MP_Y,
        (long long)CIn * MP_Y, sCI, 0LL);

    // launch 8: wy = y @ W_w^T : (b, n, 512) fp32, 3-pass bf16 (W_b cancels in BN)
    tgemm<0, 0, 3, 0><<<dim3(98, 4, BB), 256, smem>>>(y_hi, y_lo, ww_hi, ww_lo,
        wy, nullptr, nullptr, nullptr, CIn, CCH, sCI, 0LL, (long long)NN * CCH, 0LL);

    // launches 9-10: BN stats
    stats_part<<<dim3(4, 98), 128>>>(wy, part);
    stats_fin<<<1, 512>>>(part, stats);

    // launch 11: transpose + BN affine + residual
    final_kernel<<<dim3(NN / 32, CCH / 32, BB), dim3(32, 8)>>>(wy, x, gamma, beta, stats, out);
}

// round 12
// speedup vs baseline: 1.4071x; 1.1390x over previous
#include <cuda_runtime.h>
#include <cuda_bf16.h>
#include <cuda_fp16.h>
#include <stdint.h>
#include <math.h>

typedef __nv_bfloat16 bf16;
typedef unsigned int u32;

// ---------------- problem constants ----------------
#define BB 4
#define CCH 512
#define CIn 256
#define NN 12544
#define MMr 1568          // real pooled positions
#define MP_Y 1600         // pad for y-GEMM K (25*64)
#define MP_F 1664         // pad for f-GEMM N (13*128)
#define EPS 1e-5f

// ---------------- scratch layout (byte offsets) ----------------
#define XT_HI    0ULL
#define XT_LO    51380224ULL
#define F_OFF    0ULL
#define CONV_HI  334987264ULL
#define CONV_LO  412057600ULL
#define P_F16    334987264ULL   // aliases conv planes (dead by softmax time)
#define Y_F16    0ULL           // aliases f (dead after softmax)
#define WY_OFF   102760448ULL
#define GT_F16   656113664ULL   // (b,256,1600) fp16 single plane
#define PHP_HI   662667264ULL
#define PHP_LO   666075136ULL
#define W8_OFF   669483008ULL
#define BCAT_OFF 671580160ULL
#define PART_OFF 671583232ULL
#define SCRATCH_BYTES 672000000ULL

#define CONV_PLANE 25690112ULL   // bytes per conv plane (4*NN*256*2)

__device__ __align__(128) unsigned char d_scratch[SCRATCH_BYTES];
__device__ __align__(16) float d_stats[2 * CCH];

// ---------------- helpers ----------------
__device__ __forceinline__ u32 smem_u32(const void* p) {
    u32 a;
    asm("{ .reg .u64 t; cvta.to.shared.u64 t, %1; cvt.u32.u64 %0, t; }" : "=r"(a) : "l"(p));
    return a;
}
__device__ __forceinline__ void ldsm4(u32& r0, u32& r1, u32& r2, u32& r3, u32 addr) {
    asm volatile("ldmatrix.sync.aligned.m8n8.x4.shared.b16 {%0,%1,%2,%3}, [%4];"
                 : "=r"(r0), "=r"(r1), "=r"(r2), "=r"(r3) : "r"(addr));
}
template <int F16>
__device__ __forceinline__ void mma16816(float* d, const u32* a, const u32* b) {
    if (F16)
        asm volatile(
            "mma.sync.aligned.m16n8k16.row.col.f32.f16.f16.f32 "
            "{%0,%1,%2,%3},{%4,%5,%6,%7},{%8,%9},{%0,%1,%2,%3};"
            : "+f"(d[0]), "+f"(d[1]), "+f"(d[2]), "+f"(d[3])
            : "r"(a[0]), "r"(a[1]), "r"(a[2]), "r"(a[3]), "r"(b[0]), "r"(b[1]));
    else
        asm volatile(
            "mma.sync.aligned.m16n8k16.row.col.f32.bf16.bf16.f32 "
            "{%0,%1,%2,%3},{%4,%5,%6,%7},{%8,%9},{%0,%1,%2,%3};"
            : "+f"(d[0]), "+f"(d[1]), "+f"(d[2]), "+f"(d[3])
            : "r"(a[0]), "r"(a[1]), "r"(a[2]), "r"(a[3]), "r"(b[0]), "r"(b[1]));
}
__device__ __forceinline__ u32 sw128(u32 off) { return off ^ ((off >> 3) & 0x70); }
__device__ __forceinline__ void cp16(u32 dst, const void* src) {
    asm volatile("cp.async.cg.shared.global [%0], [%1], 16;" :: "r"(dst), "l"(src));
}
#define CP_COMMIT() asm volatile("cp.async.commit_group;" ::: "memory")
#define CP_WAIT1()  asm volatile("cp.async.wait_group 1;" ::: "memory")

// ---------------- cp.async split 16-bit GEMM (R7-validated core) ----------------
// Passes: 0 = A_hi*B_hi^T, 1 = A_hi*B_lo^T, 2 = A_lo*B_hi^T.
// NP=3: full 3-term split. NP=2: A_hi*(B_hi+B_lo). NP=1: plain A_hi*B_hi^T.
// A planes: (Mtot x K) 16-bit row-major. B planes: (Ntot x K) 16-bit row-major.
// CTA tile 128x128, BK=64, 8 warps (2M x 4N), 3-stage cp.async ring, 2 CTAs/SM.
// EPI 0: fp32 C + optional col bias. EPI 1: bf16 hi/lo planes. EPI 2: single fp16 plane.
// SEG 1: 256-col segmented output (fused conv). F16: fp16 mma instead of bf16.
template <int EPI, int SEG, int NP, int F16>
__global__ __launch_bounds__(256, 2)
void tgemm(const bf16* __restrict__ Ahi, const bf16* __restrict__ Alo,
           const bf16* __restrict__ Bhi, const bf16* __restrict__ Blo,
           float* __restrict__ Cf, bf16* __restrict__ Chi, bf16* __restrict__ Clo,
           const float* __restrict__ bias,
           int K, int ldc, long long sA, long long sB, long long sC, long long segS)
{
    extern __shared__ __align__(1024) unsigned char sm[];
    const u32 sbase = smem_u32(sm);
    const int tid = threadIdx.x;
    const int wid = tid >> 5;
    const int lane = tid & 31;
    const int m0 = blockIdx.x * 128;
    const int n0 = blockIdx.y * 128;
    const long long bz = blockIdx.z;
    Ahi += bz * sA; Alo += bz * sA;
    Bhi += bz * sB; Blo += bz * sB;

    const int Kc = K >> 6;
    const int total = NP * Kc;

    // ---- cp.async mapping: thread -> row (tid>>1), 4 x 16B chunks ----
    const int rowL = tid >> 1;
    const int segb = (tid & 1) * 32;     // element offset within 64-elem row
    const long long gA = (long long)(m0 + rowL) * K + segb;
    const long long gB = (long long)(n0 + rowL) * K + segb;
    u32 soff[4];
#pragma unroll
    for (int i = 0; i < 4; i++)
        soff[i] = sw128((u32)rowL * 128 + (u32)segb * 2 + i * 16);

// pass order: 0 = hi*hi, 1 = hi*lo, 2 = lo*hi (A_hi reused in passes 0,1)
#define ISSUE(it2) do { \
    const int _p = (it2) / Kc; \
    const int _k0 = ((it2) - _p * Kc) << 6; \
    const bf16* _A = (_p == 2) ? Alo : Ahi; \
    const bf16* _B = (_p == 1) ? Blo : Bhi; \
    const u32 _sa = sbase + ((it2) % 3) * 32768u; \
    const u32 _sb = _sa + 16384u; \
    _Pragma("unroll") \
    for (int _i = 0; _i < 4; _i++) { \
        cp16(_sa + soff[_i], _A + gA + _k0 + _i * 8); \
        cp16(_sb + soff[_i], _B + gB + _k0 + _i * 8); \
    } \
} while (0)

    // ---- per-lane ldmatrix bases ----
    const int wm = wid >> 2;
    const int wn = wid & 3;
    const int rowA = wm * 64 + ((lane >> 3) & 1) * 8 + (lane & 7);
    const u32 kbA = (u32)(lane >> 4) * 16;
    const int rowB = wn * 32 + ((lane >> 4) & 1) * 8 + (lane & 7);
    const u32 kbB = (u32)((lane >> 3) & 1) * 16;

    float acc[4][4][4];
#pragma unroll
    for (int mt = 0; mt < 4; mt++)
#pragma unroll
        for (int nt = 0; nt < 4; nt++)
#pragma unroll
            for (int q = 0; q < 4; q++) acc[mt][nt][q] = 0.f;

    // prologue: stages 0,1
    ISSUE(0); CP_COMMIT();
    ISSUE(1); CP_COMMIT();

    for (int it = 0; it < total; it++) {
        CP_WAIT1();
        __syncthreads();
        if (it + 2 < total) ISSUE(it + 2);
        CP_COMMIT();

        const u32 sA32 = sbase + (it % 3) * 32768u;
        const u32 sB32 = sA32 + 16384u;
#pragma unroll
        for (int kk = 0; kk < 4; kk++) {
            u32 af[4][4];
#pragma unroll
            for (int mt = 0; mt < 4; mt++) {
                u32 off = (u32)(rowA + mt * 16) * 128 + (u32)kk * 32 + kbA;
                ldsm4(af[mt][0], af[mt][1], af[mt][2], af[mt][3], sA32 + sw128(off));
            }
            u32 bfr[2][4];
#pragma unroll
            for (int nt2 = 0; nt2 < 2; nt2++) {
                u32 off = (u32)(rowB + nt2 * 16) * 128 + (u32)kk * 32 + kbB;
                ldsm4(bfr[nt2][0], bfr[nt2][1], bfr[nt2][2], bfr[nt2][3], sB32 + sw128(off));
            }
#pragma unroll
            for (int mt = 0; mt < 4; mt++)
#pragma unroll
                for (int nt = 0; nt < 4; nt++)
                    mma16816<F16>(acc[mt][nt], af[mt], &bfr[nt >> 1][(nt & 1) * 2]);
        }
    }
#undef ISSUE

    // ---- epilogue ----
    const int r0 = m0 + wm * 64 + (lane >> 2);
    const int cb0 = n0 + wn * 32 + (lane & 3) * 2;
    const long long obase = bz * sC + (SEG ? (long long)(n0 >> 8) * segS : 0LL);
#pragma unroll
    for (int nt = 0; nt < 4; nt++) {
        const int c = cb0 + nt * 8;
        const int cl = SEG ? (c & 255) : c;
        const float b0v = bias ? bias[c] : 0.f;
        const float b1v = bias ? bias[c + 1] : 0.f;
#pragma unroll
        for (int mt = 0; mt < 4; mt++) {
            const long long ra = r0 + mt * 16;
            const long long rb = ra + 8;
            float v0 = acc[mt][nt][0] + b0v;
            float v1 = acc[mt][nt][1] + b1v;
            float v2 = acc[mt][nt][2] + b0v;
            float v3 = acc[mt][nt][3] + b1v;
            if (EPI == 0) {
                float* base = Cf + obase;
                *(float2*)(base + ra * ldc + cl) = make_float2(v0, v1);
                *(float2*)(base + rb * ldc + cl) = make_float2(v2, v3);
            } else if (EPI == 2) {
                __half* hp = (__half*)Chi + obase;
                *(__half2*)(hp + ra * ldc + cl) = __floats2half2_rn(v0, v1);
                *(__half2*)(hp + rb * ldc + cl) = __floats2half2_rn(v2, v3);
            } else {
                bf16 h0 = __float2bfloat16(v0), h1 = __float2bfloat16(v1);
                bf16 h2 = __float2bfloat16(v2), h3 = __float2bfloat16(v3);
                bf16 l0 = __float2bfloat16(v0 - __bfloat162float(h0));
                bf16 l1 = __float2bfloat16(v1 - __bfloat162float(h1));
                bf16 l2 = __float2bfloat16(v2 - __bfloat162float(h2));
                bf16 l3 = __float2bfloat16(v3 - __bfloat162float(h3));
                bf16* hb = Chi + obase;
                bf16* lb = Clo + obase;
                *(u32*)(hb + ra * ldc + cl) = (u32)__bfloat16_as_ushort(h0) | ((u32)__bfloat16_as_ushort(h1) << 16);
                *(u32*)(hb + rb * ldc + cl) = (u32)__bfloat16_as_ushort(h2) | ((u32)__bfloat16_as_ushort(h3) << 16);
                *(u32*)(lb + ra * ldc + cl) = (u32)__bfloat16_as_ushort(l0) | ((u32)__bfloat16_as_ushort(l1) << 16);
                *(u32*)(lb + rb * ldc + cl) = (u32)__bfloat16_as_ushort(l2) | ((u32)__bfloat16_as_ushort(l3) << 16);
            }
        }
    }
}

// ---------------- prep: weight splits (theta/g/phi bf16, W fp16) + bias concat ----------------
__global__ void prep_kernel(const float* __restrict__ tw, const float* __restrict__ gw,
                            const float* __restrict__ pw, const float* __restrict__ ww,
                            const float* __restrict__ tb, const float* __restrict__ gb,
                            const float* __restrict__ pb,
                            bf16* __restrict__ wcat_hi, bf16* __restrict__ wcat_lo,
                            __half* __restrict__ wwhi, __half* __restrict__ wwlo,
                            float* __restrict__ bcat)
{
    const int i = blockIdx.x * 256 + threadIdx.x;   // grid 2048 -> 524288 threads
    const int t = i >> 17;                          // tensor 0..3
    const int j = i & 131071;
    const float* src = (t == 0) ? tw : (t == 1) ? gw : (t == 2) ? pw : ww;
    const float v = src[j];
    if (t < 3) {
        const bf16 h = __float2bfloat16(v);
        wcat_hi[t * 131072 + j] = h;
        wcat_lo[t * 131072 + j] = __float2bfloat16(v - __bfloat162float(h));
    } else {
        const __half h = __float2half(v);
        wwhi[j] = h;
        wwlo[j] = __float2half(v - __half2float(h));
    }
    if (i < 768) {
        const float* bs = (i < 256) ? tb : (i < 512) ? gb : pb;
        bcat[i] = bs[i & 255];
    }
}

// ---------------- zero fill ----------------
__global__ void zero_kernel(float4* __restrict__ p, long long n4)
{
    long long i = (long long)blockIdx.x * 256 + threadIdx.x;
    const long long stride = (long long)gridDim.x * 256;
    for (; i < n4; i += stride) p[i] = make_float4(0.f, 0.f, 0.f, 0.f);
}

// ---------------- transpose x (b,512,N) -> xT hi/lo (b,N,512) ----------------
__global__ void xpose_kernel(const float* __restrict__ x, bf16* __restrict__ xhi,
                             bf16* __restrict__ xlo)
{
    __shared__ float t[32][33];
    const int b = blockIdx.z;
    const int n0 = blockIdx.x * 32;
    const int c0 = blockIdx.y * 32;
    const int tx = threadIdx.x, ty = threadIdx.y;
    const float* xb = x + (long long)b * CCH * NN;
#pragma unroll
    for (int k = 0; k < 4; k++)
        t[ty + k * 8][tx] = xb[(long long)(c0 + ty + k * 8) * NN + n0 + tx];
    __syncthreads();
    bf16* hb = xhi + (long long)b * NN * CCH;
    bf16* lb = xlo + (long long)b * NN * CCH;
#pragma unroll
    for (int k = 0; k < 4; k++) {
        float v = t[tx][ty + k * 8];
        long long o = (long long)(n0 + ty + k * 8) * CCH + c0 + tx;
        bf16 h = __float2bfloat16(v);
        hb[o] = h;
        lb[o] = __float2bfloat16(v - __bfloat162float(h));
    }
}

// ---------------- 2x2x2 maxpool + split; gT -> single fp16, php -> bf16 hi/lo ----------------
__global__ void pool_kernel(const bf16* __restrict__ gH, const bf16* __restrict__ gL,
                            const bf16* __restrict__ pH, const bf16* __restrict__ pL,
                            __half* __restrict__ gT,
                            bf16* __restrict__ phphi, bf16* __restrict__ phplo)
{
    const int m = blockIdx.x;      // 0..1567
    const int b = blockIdx.y;
    const int ci = threadIdx.x;    // 0..255
    const int tp = m / 196;
    const int r = m % 196;
    const int hp = r / 14;
    const int wp = r % 14;
    const long long bb = (long long)b * NN;
    float gm = -1e30f, pm = -1e30f;
#pragma unroll
    for (int dt = 0; dt < 2; dt++)
#pragma unroll
        for (int dh = 0; dh < 2; dh++)
#pragma unroll
            for (int dw = 0; dw < 2; dw++) {
                const long long n = (long long)(2 * tp + dt) * 784 + (2 * hp + dh) * 28 + (2 * wp + dw);
                const long long o = (bb + n) * CIn + ci;
                float gv = __bfloat162float(gH[o]) + __bfloat162float(gL[o]);
                float pv = __bfloat162float(pH[o]) + __bfloat162float(pL[o]);
                gm = fmaxf(gm, gv);
                pm = fmaxf(pm, pv);
            }
    {
        long long o = ((long long)b * MP_F + m) * CIn + ci;
        bf16 h = __float2bfloat16(pm);
        phphi[o] = h;
        phplo[o] = __float2bfloat16(pm - __bfloat162float(h));
    }
    gT[((long long)b * CIn + ci) * MP_Y + m] = __float2half(gm);
}

// ---------------- softmax: single global read; writes p as one fp16 plane ----------------
__global__ __launch_bounds__(256)
void softmax_kernel(const float* __restrict__ f, __half* __restrict__ pout)
{
    __shared__ float row[MMr];
    __shared__ float red[8];
    const long long r = blockIdx.x;
    const float* p = f + r * MP_F;
    __half* oh = pout + r * MP_Y;
    const int tid = threadIdx.x;
    const int wid = tid >> 5, lane = tid & 31;

    float mx = -1e30f;
    for (int i = tid; i < MMr; i += 256) {
        float v = p[i];
        row[i] = v;
        mx = fmaxf(mx, v);
    }
#pragma unroll
    for (int s = 16; s > 0; s >>= 1) mx = fmaxf(mx, __shfl_xor_sync(~0u, mx, s));
    if (lane == 0) red[wid] = mx;
    __syncthreads();
    {
        float t = red[lane & 7];
#pragma unroll
        for (int s = 4; s > 0; s >>= 1) t = fmaxf(t, __shfl_xor_sync(~0u, t, s));
        mx = t;
    }

    float sum = 0.f;
    for (int i = tid; i < MMr; i += 256) {
        float e = __expf(row[i] - mx);
        row[i] = e;
        sum += e;
    }
#pragma unroll
    for (int s = 16; s > 0; s >>= 1) sum += __shfl_xor_sync(~0u, sum, s);
    __syncthreads();
    if (lane == 0) red[wid] = sum;
    __syncthreads();
    {
        float t = red[lane & 7];
#pragma unroll
        for (int s = 4; s > 0; s >>= 1) t += __shfl_xor_sync(~0u, t, s);
        sum = t;
    }
    const float inv = 1.f / sum;

    for (int i = tid; i < MMr; i += 256)
        oh[i] = __float2half(row[i] * inv);
    if (tid < MP_Y - MMr)
        oh[MMr + tid] = __ushort_as_half(0);
}

// ---------------- BN stats: partial sums then finalize ----------------
__global__ void stats_part(const float* __restrict__ wy, float* __restrict__ part)
{
    const int c = blockIdx.x * 128 + threadIdx.x;
    const int rb = blockIdx.y;                      // 98 row blocks of 512 rows
    const float* p = wy + (long long)rb * 512 * CCH + c;
    float s = 0.f, ss = 0.f;
    for (int r = 0; r < 512; r++) {
        float v = p[(long long)r * CCH];
        s += v;
        ss += v * v;
    }
    part[(long long)rb * 1024 + c] = s;
    part[(long long)rb * 1024 + 512 + c] = ss;
}

__global__ void stats_fin(const float* __restrict__ part, float* __restrict__ stats)
{
    const int c = threadIdx.x;   // 512
    float s = 0.f, ss = 0.f;
    for (int r = 0; r < 98; r++) {
        s += part[r * 1024 + c];
        ss += part[r * 1024 + 512 + c];
    }
    const float cnt = (float)BB * (float)NN;
    const float mean = s / cnt;
    const float var = ss / cnt - mean * mean;
    stats[c] = mean;
    stats[CCH + c] = rsqrtf(var + EPS);
}

// ---------------- final: transpose wy (b,n,c)->(b,c,n), BN affine + residual ----------------
__global__ void final_kernel(const float* __restrict__ wy, const float* __restrict__ x,
                             const float* __restrict__ gamma, const float* __restrict__ beta,
                             const float* __restrict__ stats, float* __restrict__ out)
{
    __shared__ float t[32][33];
    const int b = blockIdx.z;
    const int n0 = blockIdx.x * 32;
    const int c0 = blockIdx.y * 32;
    const int tx = threadIdx.x, ty = threadIdx.y;
    const float* wb = wy + (long long)b * NN * CCH;
#pragma unroll
    for (int k = 0; k < 4; k++)
        t[ty + k * 8][tx] = wb[(long long)(n0 + ty + k * 8) * CCH + c0 + tx];
    __syncthreads();
#pragma unroll
    for (int k = 0; k < 4; k++) {
        const int c = c0 + ty + k * 8;
        const float mean = stats[c];
        const float rstd = stats[CCH + c];
        const float gs = gamma[c] * rstd;
        const float off = beta[c] - mean * gs;
        const long long o = ((long long)b * CCH + c) * NN + n0 + tx;
        out[o] = t[tx][ty + k * 8] * gs + off + x[o];
    }
}

// ---------------- launch ----------------
extern "C" void kernel_launch(void* const* d_in, const int* in_sizes, int n_in,
                              void* d_out, int out_size)
{
    const float* x       = (const float*)d_in[0];
    const float* g_w     = (const float*)d_in[1];
    const float* g_b     = (const float*)d_in[2];
    const float* theta_w = (const float*)d_in[3];
    const float* theta_b = (const float*)d_in[4];
    const float* phi_w   = (const float*)d_in[5];
    const float* phi_b   = (const float*)d_in[6];
    const float* W_w     = (const float*)d_in[7];
    // d_in[8] = W_b: constant channel bias cancels exactly in training-mode BN — skipped.
    const float* gamma   = (const float*)d_in[9];
    const float* beta    = (const float*)d_in[10];
    float* out = (float*)d_out;

    unsigned char* S = nullptr;
    float* stats = nullptr;
    cudaGetSymbolAddress((void**)&S, d_scratch);
    cudaGetSymbolAddress((void**)&stats, d_stats);

    bf16* xt_hi  = (bf16*)(S + XT_HI);
    bf16* xt_lo  = (bf16*)(S + XT_LO);
    float* f     = (float*)(S + F_OFF);
    bf16* conv_hi = (bf16*)(S + CONV_HI);   // [theta | g | phi] planes, each (b,n,256)
    bf16* conv_lo = (bf16*)(S + CONV_LO);
    bf16* th_hi  = conv_hi;                 // seg 0
    bf16* th_lo  = conv_lo;
    bf16* gc_hi  = (bf16*)(S + CONV_HI + CONV_PLANE);       // seg 1
    bf16* gc_lo  = (bf16*)(S + CONV_LO + CONV_PLANE);
    bf16* pc_hi  = (bf16*)(S + CONV_HI + 2 * CONV_PLANE);   // seg 2
    bf16* pc_lo  = (bf16*)(S + CONV_LO + 2 * CONV_PLANE);
    __half* p16  = (__half*)(S + P_F16);                    // (b, n, 1600) fp16
    __half* y16  = (__half*)(S + Y_F16);                    // (b, n, 256) fp16
    float* wy    = (float*)(S + WY_OFF);
    __half* gt16 = (__half*)(S + GT_F16);                   // (b, 256, 1600) fp16
    bf16* php_hi = (bf16*)(S + PHP_HI);
    bf16* php_lo = (bf16*)(S + PHP_LO);
    bf16* wcat_hi = (bf16*)(S + W8_OFF);                    // 768 x 512 bf16
    bf16* wcat_lo = (bf16*)(S + W8_OFF + 786432);
    __half* ww_hi = (__half*)(S + W8_OFF + 1572864);        // 512 x 256 fp16
    __half* ww_lo = (__half*)(S + W8_OFF + 1835008);
    float* bcat  = (float*)(S + BCAT_OFF);                  // 768
    float* part  = (float*)(S + PART_OFF);

    const int smem = 3 * 32768;   // 96 KB: 3-stage ring
    cudaFuncSetAttribute(tgemm<0, 0, 3, 0>, cudaFuncAttributeMaxDynamicSharedMemorySize, smem);
    cudaFuncSetAttribute(tgemm<0, 0, 2, 1>, cudaFuncAttributeMaxDynamicSharedMemorySize, smem);
    cudaFuncSetAttribute(tgemm<2, 0, 1, 1>, cudaFuncAttributeMaxDynamicSharedMemorySize, smem);
    cudaFuncSetAttribute(tgemm<1, 1, 3, 0>, cudaFuncAttributeMaxDynamicSharedMemorySize, smem);

    const long long sXT = (long long)NN * CCH;
    const long long sCI = (long long)NN * CIn;

    // launch 0: weight splits + bias concat
    prep_kernel<<<2048, 256>>>(theta_w, g_w, phi_w, W_w, theta_b, g_b, phi_b,
                               wcat_hi, wcat_lo, ww_hi, ww_lo, bcat);

    // launch 1: zero gt/php region (covers pad rows/cols; 13,369,344 B at GT_F16)
    zero_kernel<<<2048, 256>>>((float4*)(S + GT_F16), 13369344 / 16);

    // launch 2: transpose + split x -> xT (b, n, 512)
    xpose_kernel<<<dim3(NN / 32, CCH / 32, BB), dim3(32, 8)>>>(x, xt_hi, xt_lo);

    // launch 3: fused conv [theta|g|phi] = xT @ wcat^T -> bf16 hi/lo planes
    tgemm<1, 1, 3, 0><<<dim3(98, 6, BB), 256, smem>>>(xt_hi, xt_lo, wcat_hi, wcat_lo,
        nullptr, conv_hi, conv_lo, bcat, CCH, CIn, sXT, 0LL, sCI, 4LL * sCI);

    // launch 4: pool + split: gT fp16 single plane (b,256,1600), php bf16 (b,1664,256)
    pool_kernel<<<dim3(MMr, BB), 256>>>(gc_hi, gc_lo, pc_hi, pc_lo,
                                        gt16, php_hi, php_lo);

    // launch 5 (ncu-profiled): f = theta @ phi^T : (b, n, 1664) fp32, 3-pass bf16
    tgemm<0, 0, 3, 0><<<dim3(98, MP_F / 128, BB), 256, smem>>>(th_hi, th_lo, php_hi, php_lo,
        f, nullptr, nullptr, nullptr, CIn, MP_F, sCI, (long long)MP_F * CIn,
        (long long)NN * MP_F, 0LL);

    // launch 6: softmax -> p fp16 single plane (b, n, 1600)
    softmax_kernel<<<BB * NN, 256>>>(f, p16);

    // launch 7: y = p @ gT^T : 1-pass fp16 mma -> y fp16 single plane
    tgemm<2, 0, 1, 1><<<dim3(98, 2, BB), 256, smem>>>(
        (const bf16*)p16, (const bf16*)p16, (const bf16*)gt16, (const bf16*)gt16,
        nullptr, (bf16*)y16, nullptr, nullptr, MP_Y, CIn, (long long)NN * MP_Y,
        (long long)CIn * MP_Y, sCI, 0LL);

    // launch 8: wy = y @ W_w^T : 2-pass fp16 (W split fp16 hi/lo; W_b cancels in BN)
    tgemm<0, 0, 2, 1><<<dim3(98, 4, BB), 256, smem>>>(
        (const bf16*)y16, (const bf16*)y16, (const bf16*)ww_hi, (const bf16*)ww_lo,
        wy, nullptr, nullptr, nullptr, CIn, CCH, sCI, 0LL, (long long)NN * CCH, 0LL);

    // launches 9-10: BN stats
    stats_part<<<dim3(4, 98), 128>>>(wy, part);
    stats_fin<<<1, 512>>>(part, stats);

    // launch 11: transpose + BN affine + residual
    final_kernel<<<dim3(NN / 32, CCH / 32, BB), dim3(32, 8)>>>(wy, x, gamma, beta, stats, out);
}

// round 13
// speedup vs baseline: 1.5366x; 1.0920x over previous
#include <cuda_runtime.h>
#include <cuda_bf16.h>
#include <cuda_fp16.h>
#include <stdint.h>
#include <math.h>

typedef __nv_bfloat16 bf16;
typedef unsigned int u32;

// ---------------- problem constants ----------------
#define BB 4
#define CCH 512
#define CIn 256
#define NN 12544
#define MMr 1568          // real pooled positions
#define MP_Y 1600         // pad for y-GEMM K (25*64)
#define MP_F 1664         // pad for f-GEMM N (13*128)
#define EPS 1e-5f

// ---------------- scratch layout (byte offsets) ----------------
// xT bf16 hi/lo + fp16 plane live in the front 155MB, consumed by convs;
// f (335MB) overwrites them afterwards; p16 aliases conv planes (dead after
// pool/f-GEMM); y16 aliases f (dead after softmax).
#define XT_HI    0ULL
#define XT_LO    51380224ULL
#define XT_F16   102760448ULL
#define F_OFF    0ULL
#define CONV_HI  334987264ULL                   // [theta_hi | phi_hi]
#define G16_OFF  386367488ULL                   // g conv out, fp16 single plane
#define CONV_LO  412057600ULL                   // [theta_lo | phi_lo]
#define P_F16    334987264ULL
#define Y_F16    0ULL
#define WY_OFF   102760448ULL
#define GT_F16   656113664ULL                   // (b,256,1600) fp16 single plane
#define PHP_HI   662667264ULL
#define PHP_LO   666075136ULL
#define W8_OFF   669483008ULL
#define BCAT_OFF 671580160ULL
#define PART_OFF 671583232ULL
#define SCRATCH_BYTES 672000000ULL

#define CONV_PLANE 25690112ULL   // bytes per conv plane (4*NN*256*2)

__device__ __align__(128) unsigned char d_scratch[SCRATCH_BYTES];
__device__ __align__(16) float d_stats[2 * CCH];

// ---------------- helpers ----------------
__device__ __forceinline__ u32 smem_u32(const void* p) {
    u32 a;
    asm("{ .reg .u64 t; cvta.to.shared.u64 t, %1; cvt.u32.u64 %0, t; }" : "=r"(a) : "l"(p));
    return a;
}
__device__ __forceinline__ void ldsm4(u32& r0, u32& r1, u32& r2, u32& r3, u32 addr) {
    asm volatile("ldmatrix.sync.aligned.m8n8.x4.shared.b16 {%0,%1,%2,%3}, [%4];"
                 : "=r"(r0), "=r"(r1), "=r"(r2), "=r"(r3) : "r"(addr));
}
template <int F16>
__device__ __forceinline__ void mma16816(float* d, const u32* a, const u32* b) {
    if (F16)
        asm volatile(
            "mma.sync.aligned.m16n8k16.row.col.f32.f16.f16.f32 "
            "{%0,%1,%2,%3},{%4,%5,%6,%7},{%8,%9},{%0,%1,%2,%3};"
            : "+f"(d[0]), "+f"(d[1]), "+f"(d[2]), "+f"(d[3])
            : "r"(a[0]), "r"(a[1]), "r"(a[2]), "r"(a[3]), "r"(b[0]), "r"(b[1]));
    else
        asm volatile(
            "mma.sync.aligned.m16n8k16.row.col.f32.bf16.bf16.f32 "
            "{%0,%1,%2,%3},{%4,%5,%6,%7},{%8,%9},{%0,%1,%2,%3};"
            : "+f"(d[0]), "+f"(d[1]), "+f"(d[2]), "+f"(d[3])
            : "r"(a[0]), "r"(a[1]), "r"(a[2]), "r"(a[3]), "r"(b[0]), "r"(b[1]));
}
__device__ __forceinline__ u32 sw128(u32 off) { return off ^ ((off >> 3) & 0x70); }
__device__ __forceinline__ void cp16(u32 dst, const void* src) {
    asm volatile("cp.async.cg.shared.global [%0], [%1], 16;" :: "r"(dst), "l"(src));
}
#define CP_COMMIT() asm volatile("cp.async.commit_group;" ::: "memory")
#define CP_WAIT1()  asm volatile("cp.async.wait_group 1;" ::: "memory")

// ---------------- cp.async split 16-bit GEMM (R7-validated core) ----------------
// Passes: 0 = A_hi*B_hi^T, 1 = A_hi*B_lo^T, 2 = A_lo*B_hi^T.
// NP=3: full 3-term split. NP=2: A_hi*(B_hi+B_lo). NP=1: plain A_hi*B_hi^T.
// CTA tile 128x128, BK=64, 8 warps (2M x 4N), 3-stage cp.async ring, 2 CTAs/SM.
// EPI 0: fp32 C + optional col bias. EPI 1: bf16 hi/lo planes. EPI 2: single fp16 plane.
// SEG 1: 256-col segmented output (fused conv). F16: fp16 mma instead of bf16.
template <int EPI, int SEG, int NP, int F16>
__global__ __launch_bounds__(256, 2)
void tgemm(const bf16* __restrict__ Ahi, const bf16* __restrict__ Alo,
           const bf16* __restrict__ Bhi, const bf16* __restrict__ Blo,
           float* __restrict__ Cf, bf16* __restrict__ Chi, bf16* __restrict__ Clo,
           const float* __restrict__ bias,
           int K, int ldc, long long sA, long long sB, long long sC, long long segS)
{
    extern __shared__ __align__(1024) unsigned char sm[];
    const u32 sbase = smem_u32(sm);
    const int tid = threadIdx.x;
    const int wid = tid >> 5;
    const int lane = tid & 31;
    const int m0 = blockIdx.x * 128;
    const int n0 = blockIdx.y * 128;
    const long long bz = blockIdx.z;
    Ahi += bz * sA; Alo += bz * sA;
    Bhi += bz * sB; Blo += bz * sB;

    const int Kc = K >> 6;
    const int total = NP * Kc;

    // ---- cp.async mapping: thread -> row (tid>>1), 4 x 16B chunks ----
    const int rowL = tid >> 1;
    const int segb = (tid & 1) * 32;     // element offset within 64-elem row
    const long long gA = (long long)(m0 + rowL) * K + segb;
    const long long gB = (long long)(n0 + rowL) * K + segb;
    u32 soff[4];
#pragma unroll
    for (int i = 0; i < 4; i++)
        soff[i] = sw128((u32)rowL * 128 + (u32)segb * 2 + i * 16);

// pass order: 0 = hi*hi, 1 = hi*lo, 2 = lo*hi (A_hi reused in passes 0,1)
#define ISSUE(it2) do { \
    const int _p = (it2) / Kc; \
    const int _k0 = ((it2) - _p * Kc) << 6; \
    const bf16* _A = (_p == 2) ? Alo : Ahi; \
    const bf16* _B = (_p == 1) ? Blo : Bhi; \
    const u32 _sa = sbase + ((it2) % 3) * 32768u; \
    const u32 _sb = _sa + 16384u; \
    _Pragma("unroll") \
    for (int _i = 0; _i < 4; _i++) { \
        cp16(_sa + soff[_i], _A + gA + _k0 + _i * 8); \
        cp16(_sb + soff[_i], _B + gB + _k0 + _i * 8); \
    } \
} while (0)

    // ---- per-lane ldmatrix bases ----
    const int wm = wid >> 2;
    const int wn = wid & 3;
    const int rowA = wm * 64 + ((lane >> 3) & 1) * 8 + (lane & 7);
    const u32 kbA = (u32)(lane >> 4) * 16;
    const int rowB = wn * 32 + ((lane >> 4) & 1) * 8 + (lane & 7);
    const u32 kbB = (u32)((lane >> 3) & 1) * 16;

    float acc[4][4][4];
#pragma unroll
    for (int mt = 0; mt < 4; mt++)
#pragma unroll
        for (int nt = 0; nt < 4; nt++)
#pragma unroll
            for (int q = 0; q < 4; q++) acc[mt][nt][q] = 0.f;

    // prologue: stages 0,1
    ISSUE(0); CP_COMMIT();
    ISSUE(1); CP_COMMIT();

    for (int it = 0; it < total; it++) {
        CP_WAIT1();
        __syncthreads();
        if (it + 2 < total) ISSUE(it + 2);
        CP_COMMIT();

        const u32 sA32 = sbase + (it % 3) * 32768u;
        const u32 sB32 = sA32 + 16384u;
#pragma unroll
        for (int kk = 0; kk < 4; kk++) {
            u32 af[4][4];
#pragma unroll
            for (int mt = 0; mt < 4; mt++) {
                u32 off = (u32)(rowA + mt * 16) * 128 + (u32)kk * 32 + kbA;
                ldsm4(af[mt][0], af[mt][1], af[mt][2], af[mt][3], sA32 + sw128(off));
            }
            u32 bfr[2][4];
#pragma unroll
            for (int nt2 = 0; nt2 < 2; nt2++) {
                u32 off = (u32)(rowB + nt2 * 16) * 128 + (u32)kk * 32 + kbB;
                ldsm4(bfr[nt2][0], bfr[nt2][1], bfr[nt2][2], bfr[nt2][3], sB32 + sw128(off));
            }
#pragma unroll
            for (int mt = 0; mt < 4; mt++)
#pragma unroll
                for (int nt = 0; nt < 4; nt++)
                    mma16816<F16>(acc[mt][nt], af[mt], &bfr[nt >> 1][(nt & 1) * 2]);
        }
    }
#undef ISSUE

    // ---- epilogue ----
    const int r0 = m0 + wm * 64 + (lane >> 2);
    const int cb0 = n0 + wn * 32 + (lane & 3) * 2;
    const long long obase = bz * sC + (SEG ? (long long)(n0 >> 8) * segS : 0LL);
#pragma unroll
    for (int nt = 0; nt < 4; nt++) {
        const int c = cb0 + nt * 8;
        const int cl = SEG ? (c & 255) : c;
        const float b0v = bias ? bias[c] : 0.f;
        const float b1v = bias ? bias[c + 1] : 0.f;
#pragma unroll
        for (int mt = 0; mt < 4; mt++) {
            const long long ra = r0 + mt * 16;
            const long long rb = ra + 8;
            float v0 = acc[mt][nt][0] + b0v;
            float v1 = acc[mt][nt][1] + b1v;
            float v2 = acc[mt][nt][2] + b0v;
            float v3 = acc[mt][nt][3] + b1v;
            if (EPI == 0) {
                float* base = Cf + obase;
                *(float2*)(base + ra * ldc + cl) = make_float2(v0, v1);
                *(float2*)(base + rb * ldc + cl) = make_float2(v2, v3);
            } else if (EPI == 2) {
                __half* hp = (__half*)Chi + obase;
                *(__half2*)(hp + ra * ldc + cl) = __floats2half2_rn(v0, v1);
                *(__half2*)(hp + rb * ldc + cl) = __floats2half2_rn(v2, v3);
            } else {
                bf16 h0 = __float2bfloat16(v0), h1 = __float2bfloat16(v1);
                bf16 h2 = __float2bfloat16(v2), h3 = __float2bfloat16(v3);
                bf16 l0 = __float2bfloat16(v0 - __bfloat162float(h0));
                bf16 l1 = __float2bfloat16(v1 - __bfloat162float(h1));
                bf16 l2 = __float2bfloat16(v2 - __bfloat162float(h2));
                bf16 l3 = __float2bfloat16(v3 - __bfloat162float(h3));
                bf16* hb = Chi + obase;
                bf16* lb = Clo + obase;
                *(u32*)(hb + ra * ldc + cl) = (u32)__bfloat16_as_ushort(h0) | ((u32)__bfloat16_as_ushort(h1) << 16);
                *(u32*)(hb + rb * ldc + cl) = (u32)__bfloat16_as_ushort(h2) | ((u32)__bfloat16_as_ushort(h3) << 16);
                *(u32*)(lb + ra * ldc + cl) = (u32)__bfloat16_as_ushort(l0) | ((u32)__bfloat16_as_ushort(l1) << 16);
                *(u32*)(lb + rb * ldc + cl) = (u32)__bfloat16_as_ushort(l2) | ((u32)__bfloat16_as_ushort(l3) << 16);
            }
        }
    }
}

// ---------------- prep: theta/phi bf16 hi/lo, g/W fp16 single; bias concat ----------------
__global__ void prep_kernel(const float* __restrict__ tw, const float* __restrict__ pw,
                            const float* __restrict__ gw, const float* __restrict__ ww,
                            const float* __restrict__ tb, const float* __restrict__ pb,
                            const float* __restrict__ gb,
                            bf16* __restrict__ wcat_hi, bf16* __restrict__ wcat_lo,
                            __half* __restrict__ gw16, __half* __restrict__ ww16,
                            float* __restrict__ bcat)
{
    const int i = blockIdx.x * 256 + threadIdx.x;   // grid 2048 -> 524288 threads
    const int t = i >> 17;                          // 0=theta,1=phi,2=g,3=W
    const int j = i & 131071;
    const float* src = (t == 0) ? tw : (t == 1) ? pw : (t == 2) ? gw : ww;
    const float v = src[j];
    if (t < 2) {
        const bf16 h = __float2bfloat16(v);
        wcat_hi[t * 131072 + j] = h;
        wcat_lo[t * 131072 + j] = __float2bfloat16(v - __bfloat162float(h));
    } else if (t == 2) {
        gw16[j] = __float2half(v);
    } else {
        ww16[j] = __float2half(v);
    }
    if (i < 768) {
        // bcat layout: [theta_b | phi_b | g_b]
        const float* bs = (i < 256) ? tb : (i < 512) ? pb : gb;
        bcat[i] = bs[i & 255];
    }
}

// ---------------- zero fill ----------------
__global__ void zero_kernel(float4* __restrict__ p, long long n4)
{
    long long i = (long long)blockIdx.x * 256 + threadIdx.x;
    const long long stride = (long long)gridDim.x * 256;
    for (; i < n4; i += stride) p[i] = make_float4(0.f, 0.f, 0.f, 0.f);
}

// ---------------- transpose x (b,512,N) -> xT bf16 hi/lo + fp16 plane ----------------
__global__ void xpose_kernel(const float* __restrict__ x, bf16* __restrict__ xhi,
                             bf16* __restrict__ xlo, __half* __restrict__ xf)
{
    __shared__ float t[32][33];
    const int b = blockIdx.z;
    const int n0 = blockIdx.x * 32;
    const int c0 = blockIdx.y * 32;
    const int tx = threadIdx.x, ty = threadIdx.y;
    const float* xb = x + (long long)b * CCH * NN;
#pragma unroll
    for (int k = 0; k < 4; k++)
        t[ty + k * 8][tx] = xb[(long long)(c0 + ty + k * 8) * NN + n0 + tx];
    __syncthreads();
    bf16* hb = xhi + (long long)b * NN * CCH;
    bf16* lb = xlo + (long long)b * NN * CCH;
    __half* fb = xf + (long long)b * NN * CCH;
#pragma unroll
    for (int k = 0; k < 4; k++) {
        float v = t[tx][ty + k * 8];
        long long o = (long long)(n0 + ty + k * 8) * CCH + c0 + tx;
        bf16 h = __float2bfloat16(v);
        hb[o] = h;
        lb[o] = __float2bfloat16(v - __bfloat162float(h));
        fb[o] = __float2half(v);
    }
}

// ---------------- 2x2x2 maxpool: g from fp16 plane, phi from bf16 hi/lo ----------------
__global__ void pool_kernel(const __half* __restrict__ g16,
                            const bf16* __restrict__ pH, const bf16* __restrict__ pL,
                            __half* __restrict__ gT,
                            bf16* __restrict__ phphi, bf16* __restrict__ phplo)
{
    const int m = blockIdx.x;      // 0..1567
    const int b = blockIdx.y;
    const int ci = threadIdx.x;    // 0..255
    const int tp = m / 196;
    const int r = m % 196;
    const int hp = r / 14;
    const int wp = r % 14;
    const long long bb = (long long)b * NN;
    float gm = -1e30f, pm = -1e30f;
#pragma unroll
    for (int dt = 0; dt < 2; dt++)
#pragma unroll
        for (int dh = 0; dh < 2; dh++)
#pragma unroll
            for (int dw = 0; dw < 2; dw++) {
                const long long n = (long long)(2 * tp + dt) * 784 + (2 * hp + dh) * 28 + (2 * wp + dw);
                const long long o = (bb + n) * CIn + ci;
                float gv = __half2float(g16[o]);
                float pv = __bfloat162float(pH[o]) + __bfloat162float(pL[o]);
                gm = fmaxf(gm, gv);
                pm = fmaxf(pm, pv);
            }
    {
        long long o = ((long long)b * MP_F + m) * CIn + ci;
        bf16 h = __float2bfloat16(pm);
        phphi[o] = h;
        phplo[o] = __float2bfloat16(pm - __bfloat162float(h));
    }
    gT[((long long)b * CIn + ci) * MP_Y + m] = __float2half(gm);
}

// ---------------- softmax: single global read; writes p as one fp16 plane ----------------
__global__ __launch_bounds__(256)
void softmax_kernel(const float* __restrict__ f, __half* __restrict__ pout)
{
    __shared__ float row[MMr];
    __shared__ float red[8];
    const long long r = blockIdx.x;
    const float* p = f + r * MP_F;
    __half* oh = pout + r * MP_Y;
    const int tid = threadIdx.x;
    const int wid = tid >> 5, lane = tid & 31;

    float mx = -1e30f;
    for (int i = tid; i < MMr; i += 256) {
        float v = p[i];
        row[i] = v;
        mx = fmaxf(mx, v);
    }
#pragma unroll
    for (int s = 16; s > 0; s >>= 1) mx = fmaxf(mx, __shfl_xor_sync(~0u, mx, s));
    if (lane == 0) red[wid] = mx;
    __syncthreads();
    {
        float t = red[lane & 7];
#pragma unroll
        for (int s = 4; s > 0; s >>= 1) t = fmaxf(t, __shfl_xor_sync(~0u, t, s));
        mx = t;
    }

    float sum = 0.f;
    for (int i = tid; i < MMr; i += 256) {
        float e = __expf(row[i] - mx);
        row[i] = e;
        sum += e;
    }
#pragma unroll
    for (int s = 16; s > 0; s >>= 1) sum += __shfl_xor_sync(~0u, sum, s);
    __syncthreads();
    if (lane == 0) red[wid] = sum;
    __syncthreads();
    {
        float t = red[lane & 7];
#pragma unroll
        for (int s = 4; s > 0; s >>= 1) t += __shfl_xor_sync(~0u, t, s);
        sum = t;
    }
    const float inv = 1.f / sum;

    for (int i = tid; i < MMr; i += 256)
        oh[i] = __float2half(row[i] * inv);
    if (tid < MP_Y - MMr)
        oh[MMr + tid] = __ushort_as_half(0);
}

// ---------------- BN stats: partial sums then finalize ----------------
__global__ void stats_part(const float* __restrict__ wy, float* __restrict__ part)
{
    const int c = blockIdx.x * 128 + threadIdx.x;
    const int rb = blockIdx.y;                      // 98 row blocks of 512 rows
    const float* p = wy + (long long)rb * 512 * CCH + c;
    float s = 0.f, ss = 0.f;
    for (int r = 0; r < 512; r++) {
        float v = p[(long long)r * CCH];
        s += v;
        ss += v * v;
    }
    part[(long long)rb * 1024 + c] = s;
    part[(long long)rb * 1024 + 512 + c] = ss;
}

__global__ void stats_fin(const float* __restrict__ part, float* __restrict__ stats)
{
    const int c = threadIdx.x;   // 512
    float s = 0.f, ss = 0.f;
    for (int r = 0; r < 98; r++) {
        s += part[r * 1024 + c];
        ss += part[r * 1024 + 512 + c];
    }
    const float cnt = (float)BB * (float)NN;
    const float mean = s / cnt;
    const float var = ss / cnt - mean * mean;
    stats[c] = mean;
    stats[CCH + c] = rsqrtf(var + EPS);
}

// ---------------- final: transpose wy (b,n,c)->(b,c,n), BN affine + residual ----------------
__global__ void final_kernel(const float* __restrict__ wy, const float* __restrict__ x,
                             const float* __restrict__ gamma, const float* __restrict__ beta,
                             const float* __restrict__ stats, float* __restrict__ out)
{
    __shared__ float t[32][33];
    const int b = blockIdx.z;
    const int n0 = blockIdx.x * 32;
    const int c0 = blockIdx.y * 32;
    const int tx = threadIdx.x, ty = threadIdx.y;
    const float* wb = wy + (long long)b * NN * CCH;
#pragma unroll
    for (int k = 0; k < 4; k++)
        t[ty + k * 8][tx] = wb[(long long)(n0 + ty + k * 8) * CCH + c0 + tx];
    __syncthreads();
#pragma unroll
    for (int k = 0; k < 4; k++) {
        const int c = c0 + ty + k * 8;
        const float mean = stats[c];
        const float rstd = stats[CCH + c];
        const float gs = gamma[c] * rstd;
        const float off = beta[c] - mean * gs;
        const long long o = ((long long)b * CCH + c) * NN + n0 + tx;
        out[o] = t[tx][ty + k * 8] * gs + off + x[o];
    }
}

// ---------------- launch ----------------
extern "C" void kernel_launch(void* const* d_in, const int* in_sizes, int n_in,
                              void* d_out, int out_size)
{
    const float* x       = (const float*)d_in[0];
    const float* g_w     = (const float*)d_in[1];
    const float* g_b     = (const float*)d_in[2];
    const float* theta_w = (const float*)d_in[3];
    const float* theta_b = (const float*)d_in[4];
    const float* phi_w   = (const float*)d_in[5];
    const float* phi_b   = (const float*)d_in[6];
    const float* W_w     = (const float*)d_in[7];
    // d_in[8] = W_b: constant channel bias cancels exactly in training-mode BN — skipped.
    const float* gamma   = (const float*)d_in[9];
    const float* beta    = (const float*)d_in[10];
    float* out = (float*)d_out;

    unsigned char* S = nullptr;
    float* stats = nullptr;
    cudaGetSymbolAddress((void**)&S, d_scratch);
    cudaGetSymbolAddress((void**)&stats, d_stats);

    bf16* xt_hi  = (bf16*)(S + XT_HI);
    bf16* xt_lo  = (bf16*)(S + XT_LO);
    __half* xt16 = (__half*)(S + XT_F16);
    float* f     = (float*)(S + F_OFF);
    bf16* conv_hi = (bf16*)(S + CONV_HI);   // [theta | phi] hi planes
    bf16* conv_lo = (bf16*)(S + CONV_LO);   // [theta | phi] lo planes
    bf16* th_hi  = conv_hi;                 // seg 0
    bf16* th_lo  = conv_lo;
    bf16* pc_hi  = (bf16*)(S + CONV_HI + CONV_PLANE);       // seg 1 (phi)
    bf16* pc_lo  = (bf16*)(S + CONV_LO + CONV_PLANE);
    __half* g16  = (__half*)(S + G16_OFF);                  // g conv out fp16
    __half* p16  = (__half*)(S + P_F16);                    // (b, n, 1600) fp16
    __half* y16  = (__half*)(S + Y_F16);                    // (b, n, 256) fp16
    float* wy    = (float*)(S + WY_OFF);
    __half* gt16 = (__half*)(S + GT_F16);                   // (b, 256, 1600) fp16
    bf16* php_hi = (bf16*)(S + PHP_HI);
    bf16* php_lo = (bf16*)(S + PHP_LO);
    bf16* wcat_hi = (bf16*)(S + W8_OFF);                    // 512 x 512 bf16 [theta;phi]
    bf16* wcat_lo = (bf16*)(S + W8_OFF + 524288);
    __half* gw16 = (__half*)(S + W8_OFF + 1048576);         // 256 x 512 fp16
    __half* ww16 = (__half*)(S + W8_OFF + 1310720);         // 512 x 256 fp16
    float* bcat  = (float*)(S + BCAT_OFF);                  // 768
    float* part  = (float*)(S + PART_OFF);

    const int smem = 3 * 32768;   // 96 KB: 3-stage ring
    cudaFuncSetAttribute(tgemm<0, 0, 3, 0>, cudaFuncAttributeMaxDynamicSharedMemorySize, smem);
    cudaFuncSetAttribute(tgemm<0, 0, 1, 1>, cudaFuncAttributeMaxDynamicSharedMemorySize, smem);
    cudaFuncSetAttribute(tgemm<2, 0, 1, 1>, cudaFuncAttributeMaxDynamicSharedMemorySize, smem);
    cudaFuncSetAttribute(tgemm<1, 1, 3, 0>, cudaFuncAttributeMaxDynamicSharedMemorySize, smem);

    const long long sXT = (long long)NN * CCH;
    const long long sCI = (long long)NN * CIn;

    // launch 0: weight splits + bias concat
    prep_kernel<<<2048, 256>>>(theta_w, phi_w, g_w, W_w, theta_b, phi_b, g_b,
                               wcat_hi, wcat_lo, gw16, ww16, bcat);

    // launch 1: zero gt/php region (covers pad rows/cols; 13,369,344 B at GT_F16)
    zero_kernel<<<2048, 256>>>((float4*)(S + GT_F16), 13369344 / 16);

    // launch 2: transpose x -> xT bf16 hi/lo + fp16 plane
    xpose_kernel<<<dim3(NN / 32, CCH / 32, BB), dim3(32, 8)>>>(x, xt_hi, xt_lo, xt16);

    // launch 3: fused conv [theta|phi] = xT @ wcat^T -> bf16 hi/lo planes, 3-pass
    tgemm<1, 1, 3, 0><<<dim3(98, 4, BB), 256, smem>>>(xt_hi, xt_lo, wcat_hi, wcat_lo,
        nullptr, conv_hi, conv_lo, bcat, CCH, CIn, sXT, 0LL, sCI, 4LL * sCI);

    // launch 4: g conv = x16 @ gw16^T : 1-pass fp16 -> g16 plane (bias = bcat+512)
    tgemm<2, 0, 1, 1><<<dim3(98, 2, BB), 256, smem>>>(
        (const bf16*)xt16, (const bf16*)xt16, (const bf16*)gw16, (const bf16*)gw16,
        nullptr, (bf16*)g16, nullptr, bcat + 512, CCH, CIn, sXT, 0LL, sCI, 0LL);

    // launch 5: pool: gT fp16 (b,256,1600), php bf16 (b,1664,256)
    pool_kernel<<<dim3(MMr, BB), 256>>>(g16, pc_hi, pc_lo, gt16, php_hi, php_lo);

    // launch 6: f = theta @ phi^T : (b, n, 1664) fp32, 3-pass bf16
    tgemm<0, 0, 3, 0><<<dim3(98, MP_F / 128, BB), 256, smem>>>(th_hi, th_lo, php_hi, php_lo,
        f, nullptr, nullptr, nullptr, CIn, MP_F, sCI, (long long)MP_F * CIn,
        (long long)NN * MP_F, 0LL);

    // launch 7: softmax -> p fp16 single plane (b, n, 1600)
    softmax_kernel<<<BB * NN, 256>>>(f, p16);

    // launch 8: y = p @ gT^T : 1-pass fp16 mma -> y fp16 single plane
    tgemm<2, 0, 1, 1><<<dim3(98, 2, BB), 256, smem>>>(
        (const bf16*)p16, (const bf16*)p16, (const bf16*)gt16, (const bf16*)gt16,
        nullptr, (bf16*)y16, nullptr, nullptr, MP_Y, CIn, (long long)NN * MP_Y,
        (long long)CIn * MP_Y, sCI, 0LL);

    // launch 9: wy = y @ W_w^T : 1-pass fp16 (W_b cancels in BN)
    tgemm<0, 0, 1, 1><<<dim3(98, 4, BB), 256, smem>>>(
        (const bf16*)y16, (const bf16*)y16, (const bf16*)ww16, (const bf16*)ww16,
        wy, nullptr, nullptr, nullptr, CIn, CCH, sCI, 0LL, (long long)NN * CCH, 0LL);

    // launches 10-11: BN stats
    stats_part<<<dim3(4, 98), 128>>>(wy, part);
    stats_fin<<<1, 512>>>(part, stats);

    // launch 12: transpose + BN affine + residual
    final_kernel<<<dim3(NN / 32, CCH / 32, BB), dim3(32, 8)>>>(wy, x, gamma, beta, stats, out);
}

// round 14
// speedup vs baseline: 1.6402x; 1.0675x over previous
#include <cuda_runtime.h>
#include <cuda_bf16.h>
#include <cuda_fp16.h>
#include <stdint.h>
#include <math.h>

typedef __nv_bfloat16 bf16;
typedef unsigned int u32;

// ---------------- problem constants ----------------
#define BB 4
#define CCH 512
#define CIn 256
#define NN 12544
#define MMr 1568          // real pooled positions
#define MP_Y 1600         // pad for y-GEMM K (25*64)
#define MP_F 1664         // pad for f-GEMM N (13*128)
#define EPS 1e-5f

// ---------------- scratch layout (byte offsets) ----------------
#define XT_HI    0ULL
#define XT_LO    51380224ULL
#define XT_F16   102760448ULL
#define F_OFF    0ULL
#define CONV_HI  334987264ULL                   // [theta_hi | phi_hi]
#define G16_OFF  386367488ULL                   // g conv out, fp16 single plane
#define CONV_LO  412057600ULL                   // [theta_lo | phi_lo]
#define P_F16    334987264ULL
#define Y_F16    0ULL
#define WY_OFF   102760448ULL                   // fp16 now: 51.4 MB
#define GT_F16   656113664ULL
#define PHP_HI   662667264ULL
#define PHP_LO   666075136ULL
#define W8_OFF   669483008ULL
#define BCAT_OFF 671580160ULL
#define PART_OFF 671583232ULL
#define SCRATCH_BYTES 672000000ULL

#define CONV_PLANE 25690112ULL   // bytes per conv plane (4*NN*256*2)

__device__ __align__(128) unsigned char d_scratch[SCRATCH_BYTES];
__device__ __align__(16) float d_stats[2 * CCH];

// ---------------- helpers ----------------
__device__ __forceinline__ u32 smem_u32(const void* p) {
    u32 a;
    asm("{ .reg .u64 t; cvta.to.shared.u64 t, %1; cvt.u32.u64 %0, t; }" : "=r"(a) : "l"(p));
    return a;
}
__device__ __forceinline__ void ldsm4(u32& r0, u32& r1, u32& r2, u32& r3, u32 addr) {
    asm volatile("ldmatrix.sync.aligned.m8n8.x4.shared.b16 {%0,%1,%2,%3}, [%4];"
                 : "=r"(r0), "=r"(r1), "=r"(r2), "=r"(r3) : "r"(addr));
}
template <int F16>
__device__ __forceinline__ void mma16816(float* d, const u32* a, const u32* b) {
    if (F16)
        asm volatile(
            "mma.sync.aligned.m16n8k16.row.col.f32.f16.f16.f32 "
            "{%0,%1,%2,%3},{%4,%5,%6,%7},{%8,%9},{%0,%1,%2,%3};"
            : "+f"(d[0]), "+f"(d[1]), "+f"(d[2]), "+f"(d[3])
            : "r"(a[0]), "r"(a[1]), "r"(a[2]), "r"(a[3]), "r"(b[0]), "r"(b[1]));
    else
        asm volatile(
            "mma.sync.aligned.m16n8k16.row.col.f32.bf16.bf16.f32 "
            "{%0,%1,%2,%3},{%4,%5,%6,%7},{%8,%9},{%0,%1,%2,%3};"
            : "+f"(d[0]), "+f"(d[1]), "+f"(d[2]), "+f"(d[3])
            : "r"(a[0]), "r"(a[1]), "r"(a[2]), "r"(a[3]), "r"(b[0]), "r"(b[1]));
}
__device__ __forceinline__ u32 sw128(u32 off) { return off ^ ((off >> 3) & 0x70); }
__device__ __forceinline__ void cp16(u32 dst, const void* src) {
    asm volatile("cp.async.cg.shared.global [%0], [%1], 16;" :: "r"(dst), "l"(src));
}
#define CP_COMMIT() asm volatile("cp.async.commit_group;" ::: "memory")
#define CP_WAIT1()  asm volatile("cp.async.wait_group 1;" ::: "memory")

// ---------------- cp.async split 16-bit GEMM (R7-validated core) ----------------
// Passes: 0 = A_hi*B_hi^T, 1 = A_hi*B_lo^T, 2 = A_lo*B_hi^T.
// NP=3: full 3-term split. NP=2: A_hi*(B_hi+B_lo). NP=1: plain A_hi*B_hi^T.
// CTA tile 128x128, BK=64, 8 warps (2M x 4N), 3-stage cp.async ring, 2 CTAs/SM.
// EPI 0: fp32 C + optional col bias. EPI 1: bf16 hi/lo planes. EPI 2: single fp16 plane.
// SEG 1: 256-col segmented output (fused conv). F16: fp16 mma instead of bf16.
template <int EPI, int SEG, int NP, int F16>
__global__ __launch_bounds__(256, 2)
void tgemm(const bf16* __restrict__ Ahi, const bf16* __restrict__ Alo,
           const bf16* __restrict__ Bhi, const bf16* __restrict__ Blo,
           float* __restrict__ Cf, bf16* __restrict__ Chi, bf16* __restrict__ Clo,
           const float* __restrict__ bias,
           int K, int ldc, long long sA, long long sB, long long sC, long long segS)
{
    extern __shared__ __align__(1024) unsigned char sm[];
    const u32 sbase = smem_u32(sm);
    const int tid = threadIdx.x;
    const int wid = tid >> 5;
    const int lane = tid & 31;
    const int m0 = blockIdx.x * 128;
    const int n0 = blockIdx.y * 128;
    const long long bz = blockIdx.z;
    Ahi += bz * sA; Alo += bz * sA;
    Bhi += bz * sB; Blo += bz * sB;

    const int Kc = K >> 6;
    const int total = NP * Kc;

    // ---- cp.async mapping: thread -> row (tid>>1), 4 x 16B chunks ----
    const int rowL = tid >> 1;
    const int segb = (tid & 1) * 32;     // element offset within 64-elem row
    const long long gA = (long long)(m0 + rowL) * K + segb;
    const long long gB = (long long)(n0 + rowL) * K + segb;
    u32 soff[4];
#pragma unroll
    for (int i = 0; i < 4; i++)
        soff[i] = sw128((u32)rowL * 128 + (u32)segb * 2 + i * 16);

// pass order: 0 = hi*hi, 1 = hi*lo, 2 = lo*hi (A_hi reused in passes 0,1)
#define ISSUE(it2) do { \
    const int _p = (it2) / Kc; \
    const int _k0 = ((it2) - _p * Kc) << 6; \
    const bf16* _A = (_p == 2) ? Alo : Ahi; \
    const bf16* _B = (_p == 1) ? Blo : Bhi; \
    const u32 _sa = sbase + ((it2) % 3) * 32768u; \
    const u32 _sb = _sa + 16384u; \
    _Pragma("unroll") \
    for (int _i = 0; _i < 4; _i++) { \
        cp16(_sa + soff[_i], _A + gA + _k0 + _i * 8); \
        cp16(_sb + soff[_i], _B + gB + _k0 + _i * 8); \
    } \
} while (0)

    // ---- per-lane ldmatrix bases ----
    const int wm = wid >> 2;
    const int wn = wid & 3;
    const int rowA = wm * 64 + ((lane >> 3) & 1) * 8 + (lane & 7);
    const u32 kbA = (u32)(lane >> 4) * 16;
    const int rowB = wn * 32 + ((lane >> 4) & 1) * 8 + (lane & 7);
    const u32 kbB = (u32)((lane >> 3) & 1) * 16;

    float acc[4][4][4];
#pragma unroll
    for (int mt = 0; mt < 4; mt++)
#pragma unroll
        for (int nt = 0; nt < 4; nt++)
#pragma unroll
            for (int q = 0; q < 4; q++) acc[mt][nt][q] = 0.f;

    // prologue: stages 0,1
    ISSUE(0); CP_COMMIT();
    ISSUE(1); CP_COMMIT();

    for (int it = 0; it < total; it++) {
        CP_WAIT1();
        __syncthreads();
        if (it + 2 < total) ISSUE(it + 2);
        CP_COMMIT();

        const u32 sA32 = sbase + (it % 3) * 32768u;
        const u32 sB32 = sA32 + 16384u;
#pragma unroll
        for (int kk = 0; kk < 4; kk++) {
            u32 af[4][4];
#pragma unroll
            for (int mt = 0; mt < 4; mt++) {
                u32 off = (u32)(rowA + mt * 16) * 128 + (u32)kk * 32 + kbA;
                ldsm4(af[mt][0], af[mt][1], af[mt][2], af[mt][3], sA32 + sw128(off));
            }
            u32 bfr[2][4];
#pragma unroll
            for (int nt2 = 0; nt2 < 2; nt2++) {
                u32 off = (u32)(rowB + nt2 * 16) * 128 + (u32)kk * 32 + kbB;
                ldsm4(bfr[nt2][0], bfr[nt2][1], bfr[nt2][2], bfr[nt2][3], sB32 + sw128(off));
            }
#pragma unroll
            for (int mt = 0; mt < 4; mt++)
#pragma unroll
                for (int nt = 0; nt < 4; nt++)
                    mma16816<F16>(acc[mt][nt], af[mt], &bfr[nt >> 1][(nt & 1) * 2]);
        }
    }
#undef ISSUE

    // ---- epilogue ----
    const int r0 = m0 + wm * 64 + (lane >> 2);
    const int cb0 = n0 + wn * 32 + (lane & 3) * 2;
    const long long obase = bz * sC + (SEG ? (long long)(n0 >> 8) * segS : 0LL);
#pragma unroll
    for (int nt = 0; nt < 4; nt++) {
        const int c = cb0 + nt * 8;
        const int cl = SEG ? (c & 255) : c;
        const float b0v = bias ? bias[c] : 0.f;
        const float b1v = bias ? bias[c + 1] : 0.f;
#pragma unroll
        for (int mt = 0; mt < 4; mt++) {
            const long long ra = r0 + mt * 16;
            const long long rb = ra + 8;
            float v0 = acc[mt][nt][0] + b0v;
            float v1 = acc[mt][nt][1] + b1v;
            float v2 = acc[mt][nt][2] + b0v;
            float v3 = acc[mt][nt][3] + b1v;
            if (EPI == 0) {
                float* base = Cf + obase;
                *(float2*)(base + ra * ldc + cl) = make_float2(v0, v1);
                *(float2*)(base + rb * ldc + cl) = make_float2(v2, v3);
            } else if (EPI == 2) {
                __half* hp = (__half*)Chi + obase;
                *(__half2*)(hp + ra * ldc + cl) = __floats2half2_rn(v0, v1);
                *(__half2*)(hp + rb * ldc + cl) = __floats2half2_rn(v2, v3);
            } else {
                bf16 h0 = __float2bfloat16(v0), h1 = __float2bfloat16(v1);
                bf16 h2 = __float2bfloat16(v2), h3 = __float2bfloat16(v3);
                bf16 l0 = __float2bfloat16(v0 - __bfloat162float(h0));
                bf16 l1 = __float2bfloat16(v1 - __bfloat162float(h1));
                bf16 l2 = __float2bfloat16(v2 - __bfloat162float(h2));
                bf16 l3 = __float2bfloat16(v3 - __bfloat162float(h3));
                bf16* hb = Chi + obase;
                bf16* lb = Clo + obase;
                *(u32*)(hb + ra * ldc + cl) = (u32)__bfloat16_as_ushort(h0) | ((u32)__bfloat16_as_ushort(h1) << 16);
                *(u32*)(hb + rb * ldc + cl) = (u32)__bfloat16_as_ushort(h2) | ((u32)__bfloat16_as_ushort(h3) << 16);
                *(u32*)(lb + ra * ldc + cl) = (u32)__bfloat16_as_ushort(l0) | ((u32)__bfloat16_as_ushort(l1) << 16);
                *(u32*)(lb + rb * ldc + cl) = (u32)__bfloat16_as_ushort(l2) | ((u32)__bfloat16_as_ushort(l3) << 16);
            }
        }
    }
}

// ---------------- prep: theta/phi bf16 hi/lo, g/W fp16 single; bias concat ----------------
__global__ void prep_kernel(const float* __restrict__ tw, const float* __restrict__ pw,
                            const float* __restrict__ gw, const float* __restrict__ ww,
                            const float* __restrict__ tb, const float* __restrict__ pb,
                            const float* __restrict__ gb,
                            bf16* __restrict__ wcat_hi, bf16* __restrict__ wcat_lo,
                            __half* __restrict__ gw16, __half* __restrict__ ww16,
                            float* __restrict__ bcat)
{
    const int i = blockIdx.x * 256 + threadIdx.x;   // grid 2048 -> 524288 threads
    const int t = i >> 17;                          // 0=theta,1=phi,2=g,3=W
    const int j = i & 131071;
    const float* src = (t == 0) ? tw : (t == 1) ? pw : (t == 2) ? gw : ww;
    const float v = src[j];
    if (t < 2) {
        const bf16 h = __float2bfloat16(v);
        wcat_hi[t * 131072 + j] = h;
        wcat_lo[t * 131072 + j] = __float2bfloat16(v - __bfloat162float(h));
    } else if (t == 2) {
        gw16[j] = __float2half(v);
    } else {
        ww16[j] = __float2half(v);
    }
    if (i < 768) {
        // bcat layout: [theta_b | phi_b | g_b]
        const float* bs = (i < 256) ? tb : (i < 512) ? pb : gb;
        bcat[i] = bs[i & 255];
    }
}

// ---------------- zero fill ----------------
__global__ void zero_kernel(float4* __restrict__ p, long long n4)
{
    long long i = (long long)blockIdx.x * 256 + threadIdx.x;
    const long long stride = (long long)gridDim.x * 256;
    for (; i < n4; i += stride) p[i] = make_float4(0.f, 0.f, 0.f, 0.f);
}

// ---------------- transpose x (b,512,N) -> xT bf16 hi/lo + fp16 plane ----------------
__global__ void xpose_kernel(const float* __restrict__ x, bf16* __restrict__ xhi,
                             bf16* __restrict__ xlo, __half* __restrict__ xf)
{
    __shared__ float t[32][33];
    const int b = blockIdx.z;
    const int n0 = blockIdx.x * 32;
    const int c0 = blockIdx.y * 32;
    const int tx = threadIdx.x, ty = threadIdx.y;
    const float* xb = x + (long long)b * CCH * NN;
#pragma unroll
    for (int k = 0; k < 4; k++)
        t[ty + k * 8][tx] = xb[(long long)(c0 + ty + k * 8) * NN + n0 + tx];
    __syncthreads();
    bf16* hb = xhi + (long long)b * NN * CCH;
    bf16* lb = xlo + (long long)b * NN * CCH;
    __half* fb = xf + (long long)b * NN * CCH;
#pragma unroll
    for (int k = 0; k < 4; k++) {
        float v = t[tx][ty + k * 8];
        long long o = (long long)(n0 + ty + k * 8) * CCH + c0 + tx;
        bf16 h = __float2bfloat16(v);
        hb[o] = h;
        lb[o] = __float2bfloat16(v - __bfloat162float(h));
        fb[o] = __float2half(v);
    }
}

// ---------------- 2x2x2 maxpool: g from fp16 plane, phi from bf16 hi/lo ----------------
__global__ void pool_kernel(const __half* __restrict__ g16,
                            const bf16* __restrict__ pH, const bf16* __restrict__ pL,
                            __half* __restrict__ gT,
                            bf16* __restrict__ phphi, bf16* __restrict__ phplo)
{
    const int m = blockIdx.x;      // 0..1567
    const int b = blockIdx.y;
    const int ci = threadIdx.x;    // 0..255
    const int tp = m / 196;
    const int r = m % 196;
    const int hp = r / 14;
    const int wp = r % 14;
    const long long bb = (long long)b * NN;
    float gm = -1e30f, pm = -1e30f;
#pragma unroll
    for (int dt = 0; dt < 2; dt++)
#pragma unroll
        for (int dh = 0; dh < 2; dh++)
#pragma unroll
            for (int dw = 0; dw < 2; dw++) {
                const long long n = (long long)(2 * tp + dt) * 784 + (2 * hp + dh) * 28 + (2 * wp + dw);
                const long long o = (bb + n) * CIn + ci;
                float gv = __half2float(g16[o]);
                float pv = __bfloat162float(pH[o]) + __bfloat162float(pL[o]);
                gm = fmaxf(gm, gv);
                pm = fmaxf(pm, pv);
            }
    {
        long long o = ((long long)b * MP_F + m) * CIn + ci;
        bf16 h = __float2bfloat16(pm);
        phphi[o] = h;
        phplo[o] = __float2bfloat16(pm - __bfloat162float(h));
    }
    gT[((long long)b * CIn + ci) * MP_Y + m] = __float2half(gm);
}

// ---------------- softmax: float4 reads; writes p as one fp16 plane ----------------
__global__ __launch_bounds__(256)
void softmax_kernel(const float* __restrict__ f, __half* __restrict__ pout)
{
    __shared__ float row[MMr];
    __shared__ float red[8];
    const long long r = blockIdx.x;
    const float* p = f + r * MP_F;
    __half* oh = pout + r * MP_Y;
    const int tid = threadIdx.x;
    const int wid = tid >> 5, lane = tid & 31;

    float mx = -1e30f;
    // 1568 = 392 float4; 256 threads: iters 0..1 (full), thread<136 on iter 1
    for (int i4 = tid; i4 < MMr / 4; i4 += 256) {
        float4 v = ((const float4*)p)[i4];
        *(float4*)&row[i4 * 4] = v;
        mx = fmaxf(fmaxf(mx, fmaxf(v.x, v.y)), fmaxf(v.z, v.w));
    }
#pragma unroll
    for (int s = 16; s > 0; s >>= 1) mx = fmaxf(mx, __shfl_xor_sync(~0u, mx, s));
    if (lane == 0) red[wid] = mx;
    __syncthreads();
    {
        float t = red[lane & 7];
#pragma unroll
        for (int s = 4; s > 0; s >>= 1) t = fmaxf(t, __shfl_xor_sync(~0u, t, s));
        mx = t;
    }

    float sum = 0.f;
    for (int i = tid; i < MMr; i += 256) {
        float e = __expf(row[i] - mx);
        row[i] = e;
        sum += e;
    }
#pragma unroll
    for (int s = 16; s > 0; s >>= 1) sum += __shfl_xor_sync(~0u, sum, s);
    __syncthreads();
    if (lane == 0) red[wid] = sum;
    __syncthreads();
    {
        float t = red[lane & 7];
#pragma unroll
        for (int s = 4; s > 0; s >>= 1) t += __shfl_xor_sync(~0u, t, s);
        sum = t;
    }
    const float inv = 1.f / sum;

    for (int i = tid; i < MMr; i += 256)
        oh[i] = __float2half(row[i] * inv);
    if (tid < MP_Y - MMr)
        oh[MMr + tid] = __ushort_as_half(0);
}

// ---------------- BN stats from fp16 wy ----------------
__global__ void stats_part(const __half* __restrict__ wy, float* __restrict__ part)
{
    const int c = blockIdx.x * 128 + threadIdx.x;
    const int rb = blockIdx.y;                      // 98 row blocks of 512 rows
    const __half* p = wy + (long long)rb * 512 * CCH + c;
    float s = 0.f, ss = 0.f;
    for (int r = 0; r < 512; r++) {
        float v = __half2float(p[(long long)r * CCH]);
        s += v;
        ss += v * v;
    }
    part[(long long)rb * 1024 + c] = s;
    part[(long long)rb * 1024 + 512 + c] = ss;
}

__global__ void stats_fin(const float* __restrict__ part, float* __restrict__ stats)
{
    const int c = threadIdx.x;   // 512
    float s = 0.f, ss = 0.f;
    for (int r = 0; r < 98; r++) {
        s += part[r * 1024 + c];
        ss += part[r * 1024 + 512 + c];
    }
    const float cnt = (float)BB * (float)NN;
    const float mean = s / cnt;
    const float var = ss / cnt - mean * mean;
    stats[c] = mean;
    stats[CCH + c] = rsqrtf(var + EPS);
}

// ---------------- final: transpose fp16 wy (b,n,c)->(b,c,n), BN affine + residual ----------------
__global__ void final_kernel(const __half* __restrict__ wy, const float* __restrict__ x,
                             const float* __restrict__ gamma, const float* __restrict__ beta,
                             const float* __restrict__ stats, float* __restrict__ out)
{
    __shared__ __half t[32][34];
    const int b = blockIdx.z;
    const int n0 = blockIdx.x * 32;
    const int c0 = blockIdx.y * 32;
    const int tx = threadIdx.x, ty = threadIdx.y;
    const __half* wb = wy + (long long)b * NN * CCH;
#pragma unroll
    for (int k = 0; k < 4; k++)
        t[ty + k * 8][tx] = wb[(long long)(n0 + ty + k * 8) * CCH + c0 + tx];
    __syncthreads();
#pragma unroll
    for (int k = 0; k < 4; k++) {
        const int c = c0 + ty + k * 8;
        const float mean = stats[c];
        const float rstd = stats[CCH + c];
        const float gs = gamma[c] * rstd;
        const float off = beta[c] - mean * gs;
        const long long o = ((long long)b * CCH + c) * NN + n0 + tx;
        out[o] = __half2float(t[tx][ty + k * 8]) * gs + off + x[o];
    }
}

// ---------------- launch ----------------
extern "C" void kernel_launch(void* const* d_in, const int* in_sizes, int n_in,
                              void* d_out, int out_size)
{
    const float* x       = (const float*)d_in[0];
    const float* g_w     = (const float*)d_in[1];
    const float* g_b     = (const float*)d_in[2];
    const float* theta_w = (const float*)d_in[3];
    const float* theta_b = (const float*)d_in[4];
    const float* phi_w   = (const float*)d_in[5];
    const float* phi_b   = (const float*)d_in[6];
    const float* W_w     = (const float*)d_in[7];
    // d_in[8] = W_b: constant channel bias cancels exactly in training-mode BN — skipped.
    const float* gamma   = (const float*)d_in[9];
    const float* beta    = (const float*)d_in[10];
    float* out = (float*)d_out;

    unsigned char* S = nullptr;
    float* stats = nullptr;
    cudaGetSymbolAddress((void**)&S, d_scratch);
    cudaGetSymbolAddress((void**)&stats, d_stats);

    bf16* xt_hi  = (bf16*)(S + XT_HI);
    bf16* xt_lo  = (bf16*)(S + XT_LO);
    __half* xt16 = (__half*)(S + XT_F16);
    float* f     = (float*)(S + F_OFF);
    bf16* conv_hi = (bf16*)(S + CONV_HI);   // [theta | phi] hi planes
    bf16* conv_lo = (bf16*)(S + CONV_LO);   // [theta | phi] lo planes
    bf16* th_hi  = conv_hi;                 // seg 0
    bf16* th_lo  = conv_lo;
    bf16* pc_hi  = (bf16*)(S + CONV_HI + CONV_PLANE);       // seg 1 (phi)
    bf16* pc_lo  = (bf16*)(S + CONV_LO + CONV_PLANE);
    __half* g16  = (__half*)(S + G16_OFF);                  // g conv out fp16
    __half* p16  = (__half*)(S + P_F16);                    // (b, n, 1600) fp16
    __half* y16  = (__half*)(S + Y_F16);                    // (b, n, 256) fp16
    __half* wy   = (__half*)(S + WY_OFF);                   // (b, n, 512) fp16
    __half* gt16 = (__half*)(S + GT_F16);                   // (b, 256, 1600) fp16
    bf16* php_hi = (bf16*)(S + PHP_HI);
    bf16* php_lo = (bf16*)(S + PHP_LO);
    bf16* wcat_hi = (bf16*)(S + W8_OFF);                    // 512 x 512 bf16 [theta;phi]
    bf16* wcat_lo = (bf16*)(S + W8_OFF + 524288);
    __half* gw16 = (__half*)(S + W8_OFF + 1048576);         // 256 x 512 fp16
    __half* ww16 = (__half*)(S + W8_OFF + 1310720);         // 512 x 256 fp16
    float* bcat  = (float*)(S + BCAT_OFF);                  // 768
    float* part  = (float*)(S + PART_OFF);

    const int smem = 3 * 32768;   // 96 KB: 3-stage ring
    cudaFuncSetAttribute(tgemm<0, 0, 3, 0>, cudaFuncAttributeMaxDynamicSharedMemorySize, smem);
    cudaFuncSetAttribute(tgemm<2, 0, 1, 1>, cudaFuncAttributeMaxDynamicSharedMemorySize, smem);
    cudaFuncSetAttribute(tgemm<1, 1, 3, 0>, cudaFuncAttributeMaxDynamicSharedMemorySize, smem);

    const long long sXT = (long long)NN * CCH;
    const long long sCI = (long long)NN * CIn;

    // launch 0: weight splits + bias concat
    prep_kernel<<<2048, 256>>>(theta_w, phi_w, g_w, W_w, theta_b, phi_b, g_b,
                               wcat_hi, wcat_lo, gw16, ww16, bcat);

    // launch 1: zero gt/php region (covers pad rows/cols; 13,369,344 B at GT_F16)
    zero_kernel<<<2048, 256>>>((float4*)(S + GT_F16), 13369344 / 16);

    // launch 2: transpose x -> xT bf16 hi/lo + fp16 plane
    xpose_kernel<<<dim3(NN / 32, CCH / 32, BB), dim3(32, 8)>>>(x, xt_hi, xt_lo, xt16);

    // launch 3: fused conv [theta|phi] = xT @ wcat^T -> bf16 hi/lo planes, 3-pass
    tgemm<1, 1, 3, 0><<<dim3(98, 4, BB), 256, smem>>>(xt_hi, xt_lo, wcat_hi, wcat_lo,
        nullptr, conv_hi, conv_lo, bcat, CCH, CIn, sXT, 0LL, sCI, 4LL * sCI);

    // launch 4: g conv = x16 @ gw16^T : 1-pass fp16 -> g16 plane (bias = bcat+512)
    tgemm<2, 0, 1, 1><<<dim3(98, 2, BB), 256, smem>>>(
        (const bf16*)xt16, (const bf16*)xt16, (const bf16*)gw16, (const bf16*)gw16,
        nullptr, (bf16*)g16, nullptr, bcat + 512, CCH, CIn, sXT, 0LL, sCI, 0LL);

    // launch 5: pool: gT fp16 (b,256,1600), php bf16 (b,1664,256)
    pool_kernel<<<dim3(MMr, BB), 256>>>(g16, pc_hi, pc_lo, gt16, php_hi, php_lo);

    // launch 6: f = theta @ phi^T : (b, n, 1664) fp32, 3-pass bf16
    tgemm<0, 0, 3, 0><<<dim3(98, MP_F / 128, BB), 256, smem>>>(th_hi, th_lo, php_hi, php_lo,
        f, nullptr, nullptr, nullptr, CIn, MP_F, sCI, (long long)MP_F * CIn,
        (long long)NN * MP_F, 0LL);

    // launch 7: softmax -> p fp16 single plane (b, n, 1600)
    softmax_kernel<<<BB * NN, 256>>>(f, p16);

    // launch 8: y = p @ gT^T : 1-pass fp16 mma -> y fp16 single plane
    tgemm<2, 0, 1, 1><<<dim3(98, 2, BB), 256, smem>>>(
        (const bf16*)p16, (const bf16*)p16, (const bf16*)gt16, (const bf16*)gt16,
        nullptr, (bf16*)y16, nullptr, nullptr, MP_Y, CIn, (long long)NN * MP_Y,
        (long long)CIn * MP_Y, sCI, 0LL);

    // launch 9: wy = y @ W_w^T : 1-pass fp16 -> fp16 wy (W_b cancels in BN)
    tgemm<2, 0, 1, 1><<<dim3(98, 4, BB), 256, smem>>>(
        (const bf16*)y16, (const bf16*)y16, (const bf16*)ww16, (const bf16*)ww16,
        nullptr, (bf16*)wy, nullptr, nullptr, CIn, CCH, sCI, 0LL, (long long)NN * CCH, 0LL);

    // launches 10-11: BN stats (from fp16 wy)
    stats_part<<<dim3(4, 98), 128>>>(wy, part);
    stats_fin<<<1, 512>>>(part, stats);

    // launch 12: transpose + BN affine + residual (fp16 wy)
    final_kernel<<<dim3(NN / 32, CCH / 32, BB), dim3(32, 8)>>>(wy, x, gamma, beta, stats, out);
}